// round 2
// baseline (speedup 1.0000x reference)
#include <cuda_runtime.h>
#include <math.h>

#define Bsz 4
#define SRCL 256
#define TGTL 512
#define DMODEL 1024
#define NHEAD 16
#define DKH 64
#define NLAYER 8
#define DFF 4096
#define VOC 32000
#define NQ (Bsz*TGTL)   // 2048 decoder token rows
#define NE (Bsz*SRCL)   // 1024 encoder token rows

// ---------------- scratch (device globals; no allocations allowed) ----------
__device__ float g_x[NQ*DMODEL];
__device__ float g_enc[NE*DMODEL];
__device__ float g_q[NQ*DMODEL];
__device__ float g_k[NQ*DMODEL];
__device__ float g_v[NQ*DMODEL];
__device__ float g_attn[NQ*DMODEL];
__device__ float g_proj[NQ*DMODEL];
__device__ float g_ffn[NQ*DFF];
__device__ float g_sc[(size_t)Bsz*NHEAD*TGTL*TGTL];

// ---------------- helpers ---------------------------------------------------
__device__ __forceinline__ float blkReduceSum(float v) {
    #pragma unroll
    for (int o = 16; o > 0; o >>= 1) v += __shfl_xor_sync(0xffffffffu, v, o);
    __shared__ float sm[8];
    int w = threadIdx.x >> 5, ln = threadIdx.x & 31;
    __syncthreads();
    if (ln == 0) sm[w] = v;
    __syncthreads();
    float r = sm[0];
    #pragma unroll
    for (int i = 1; i < 8; i++) r += sm[i];
    return r;
}

__device__ __forceinline__ float blkReduceMax(float v) {
    #pragma unroll
    for (int o = 16; o > 0; o >>= 1) v = fmaxf(v, __shfl_xor_sync(0xffffffffu, v, o));
    __shared__ float sm[8];
    int w = threadIdx.x >> 5, ln = threadIdx.x & 31;
    __syncthreads();
    if (ln == 0) sm[w] = v;
    __syncthreads();
    float r = sm[0];
    #pragma unroll
    for (int i = 1; i < 8; i++) r = fmaxf(r, sm[i]);
    return r;
}

// positional encoding value for (pos, dim)
__device__ __forceinline__ float pe_val(int pos, int d) {
    // div = exp((d & ~1) * (-ln(10000)/D))
    float div = expf((float)(d & ~1) * (-9.210340371976184f / 1024.0f));
    float ang = (float)pos * div;
    return (d & 1) ? cosf(ang) : sinf(ang);
}

// ---------------- embedding / encoder PE ------------------------------------
__global__ void embed_kernel(const int* __restrict__ tgt,
                             const float* __restrict__ emb,
                             float* __restrict__ x) {
    int row = blockIdx.x;           // 0..NQ-1
    int t = row % TGTL;
    int tok = tgt[row];
    const float* er = emb + (size_t)tok * DMODEL;
    float* xr = x + (size_t)row * DMODEL;
    for (int d = threadIdx.x; d < DMODEL; d += blockDim.x)
        xr[d] = er[d] + pe_val(t, d);
}

__global__ void encpe_kernel(const float* __restrict__ src,
                             float* __restrict__ enc) {
    int row = blockIdx.x;           // 0..NE-1
    int s = row % SRCL;
    const float* sr = src + (size_t)row * DMODEL;
    float* er = enc + (size_t)row * DMODEL;
    for (int d = threadIdx.x; d < DMODEL; d += blockDim.x)
        er[d] = sr[d] + pe_val(s, d);
}

// ---------------- SGEMM: C[M,N] = A[M,K] @ W[K,N] + bias (opt relu) ---------
// 64x64 tile, BK=16, 256 threads, 4x4 per thread. M,N mult of 64; K mult of 16.
__global__ void sgemm(const float* __restrict__ A, const float* __restrict__ W,
                      const float* __restrict__ bias, float* __restrict__ C,
                      int M, int N, int K, int relu) {
    __shared__ float As[16][64];
    __shared__ float Bs[16][64];
    int tid = threadIdx.x;
    int tx = tid & 15, ty = tid >> 4;
    int m0 = blockIdx.y * 64, n0 = blockIdx.x * 64;

    int arow = tid >> 2, acg = tid & 3;          // A: row 0..63, 4-float group
    int brow = tid >> 4, bcol = (tid & 15) * 4;  // W: row 0..15, col group
    const float* Aptr = A + (size_t)(m0 + arow) * K + acg * 4;
    const float* Wptr = W + (size_t)brow * N + n0 + bcol;

    float acc[4][4] = {};
    for (int k0 = 0; k0 < K; k0 += 16) {
        float4 a = *(const float4*)(Aptr + k0);
        float4 b = *(const float4*)(Wptr + (size_t)k0 * N);
        As[acg * 4 + 0][arow] = a.x;
        As[acg * 4 + 1][arow] = a.y;
        As[acg * 4 + 2][arow] = a.z;
        As[acg * 4 + 3][arow] = a.w;
        *(float4*)&Bs[brow][bcol] = b;
        __syncthreads();
        #pragma unroll
        for (int k = 0; k < 16; k++) {
            float4 av = *(const float4*)&As[k][ty * 4];
            float4 bv = *(const float4*)&Bs[k][tx * 4];
            float ar[4] = {av.x, av.y, av.z, av.w};
            float br[4] = {bv.x, bv.y, bv.z, bv.w};
            #pragma unroll
            for (int i = 0; i < 4; i++)
                #pragma unroll
                for (int j = 0; j < 4; j++)
                    acc[i][j] = fmaf(ar[i], br[j], acc[i][j]);
        }
        __syncthreads();
    }
    float4 bb = *(const float4*)(bias + n0 + tx * 4);
    float bias4[4] = {bb.x, bb.y, bb.z, bb.w};
    #pragma unroll
    for (int i = 0; i < 4; i++) {
        int m = m0 + ty * 4 + i;
        float4 o;
        o.x = acc[i][0] + bias4[0];
        o.y = acc[i][1] + bias4[1];
        o.z = acc[i][2] + bias4[2];
        o.w = acc[i][3] + bias4[3];
        if (relu) {
            o.x = fmaxf(o.x, 0.f); o.y = fmaxf(o.y, 0.f);
            o.z = fmaxf(o.z, 0.f); o.w = fmaxf(o.w, 0.f);
        }
        *(float4*)(C + (size_t)m * N + n0 + tx * 4) = o;
    }
}

// ---------------- attention scores: S = Q K^T / 8 (+mask) -------------------
// grid: (tilesQ*tilesK, NHEAD, Bsz); block 256. Tiles 64x64, dk=64.
__global__ void attn_scores(const float* __restrict__ Q, const float* __restrict__ Kp,
                            float* __restrict__ S, int Sk, int causal,
                            const int* __restrict__ tgt) {
    int tk = Sk >> 6;
    int qt = blockIdx.x / tk, kt = blockIdx.x % tk;
    int h = blockIdx.y, b = blockIdx.z;
    __shared__ float Qs[64][64];   // transposed: [d][m]
    __shared__ float Ks[64][64];   // transposed: [d][n]
    int tid = threadIdx.x;
    int tx = tid & 15, ty = tid >> 4;
    int r = tid >> 2, cg = tid & 3;

    const float* qbase = Q + (size_t)(b * TGTL + qt * 64 + r) * DMODEL + h * 64 + cg * 16;
    const float* kbase = Kp + (size_t)(b * Sk + kt * 64 + r) * DMODEL + h * 64 + cg * 16;
    #pragma unroll
    for (int u = 0; u < 4; u++) {
        float4 a = *(const float4*)(qbase + u * 4);
        int c = cg * 16 + u * 4;
        Qs[c + 0][r] = a.x; Qs[c + 1][r] = a.y; Qs[c + 2][r] = a.z; Qs[c + 3][r] = a.w;
        float4 kk = *(const float4*)(kbase + u * 4);
        Ks[c + 0][r] = kk.x; Ks[c + 1][r] = kk.y; Ks[c + 2][r] = kk.z; Ks[c + 3][r] = kk.w;
    }
    __syncthreads();

    float acc[4][4] = {};
    #pragma unroll
    for (int d = 0; d < 64; d++) {
        float4 av = *(const float4*)&Qs[d][ty * 4];
        float4 bv = *(const float4*)&Ks[d][tx * 4];
        float ar[4] = {av.x, av.y, av.z, av.w};
        float br[4] = {bv.x, bv.y, bv.z, bv.w};
        #pragma unroll
        for (int i = 0; i < 4; i++)
            #pragma unroll
            for (int j = 0; j < 4; j++)
                acc[i][j] = fmaf(ar[i], br[j], acc[i][j]);
    }

    float* srow = S + ((size_t)(b * NHEAD + h) * TGTL) * Sk;
    #pragma unroll
    for (int i = 0; i < 4; i++) {
        int gi = qt * 64 + ty * 4 + i;
        int rowok = 1;
        if (causal) rowok = (tgt[b * TGTL + gi] != 0);
        #pragma unroll
        for (int j = 0; j < 4; j++) {
            int gj = kt * 64 + tx * 4 + j;
            float v = acc[i][j] * 0.125f;
            if (causal && (gj > gi || !rowok)) v = -1e9f;
            srow[(size_t)gi * Sk + gj] = v;
        }
    }
}

// ---------------- row softmax (in place) ------------------------------------
__global__ void softmax_rows(float* __restrict__ S, int Sk) {
    float* row = S + (size_t)blockIdx.x * Sk;
    int tid = threadIdx.x;
    float e[2];
    int n = Sk >> 8;                // 1 or 2 elems per thread (Sk 256/512)
    float m = -3.4e38f;
    for (int u = 0; u < n; u++) m = fmaxf(m, row[tid + u * 256]);
    m = blkReduceMax(m);
    float s = 0.f;
    for (int u = 0; u < n; u++) { e[u] = expf(row[tid + u * 256] - m); s += e[u]; }
    s = blkReduceSum(s);
    float inv = 1.0f / s;
    for (int u = 0; u < n; u++) row[tid + u * 256] = e[u] * inv;
}

// ---------------- attention output: O = P @ V -------------------------------
// grid: (TGTL/64, NHEAD, Bsz); block 256; loop Sk in 64-chunks.
__global__ void attn_pv(const float* __restrict__ P, const float* __restrict__ V,
                        float* __restrict__ O, int Sk) {
    int qt = blockIdx.x, h = blockIdx.y, b = blockIdx.z;
    __shared__ float Ps[64][64];   // transposed: [j][i]
    __shared__ float Vs[64][64];   // [j][d]
    int tid = threadIdx.x;
    int tx = tid & 15, ty = tid >> 4;
    int r = tid >> 2, cg = tid & 3;

    const float* pbase = P + ((size_t)(b * NHEAD + h) * TGTL + qt * 64 + r) * Sk;
    float acc[4][4] = {};
    for (int kc = 0; kc < Sk; kc += 64) {
        #pragma unroll
        for (int u = 0; u < 4; u++) {
            int c = cg * 16 + u * 4;
            float4 p = *(const float4*)(pbase + kc + c);
            Ps[c + 0][r] = p.x; Ps[c + 1][r] = p.y; Ps[c + 2][r] = p.z; Ps[c + 3][r] = p.w;
            float4 vv = *(const float4*)(V + (size_t)(b * Sk + kc + r) * DMODEL + h * 64 + c);
            *(float4*)&Vs[r][c] = vv;
        }
        __syncthreads();
        #pragma unroll
        for (int j = 0; j < 64; j++) {
            float4 av = *(const float4*)&Ps[j][ty * 4];
            float4 bv = *(const float4*)&Vs[j][tx * 4];
            float ar[4] = {av.x, av.y, av.z, av.w};
            float br[4] = {bv.x, bv.y, bv.z, bv.w};
            #pragma unroll
            for (int i = 0; i < 4; i++)
                #pragma unroll
                for (int jj = 0; jj < 4; jj++)
                    acc[i][jj] = fmaf(ar[i], br[jj], acc[i][jj]);
        }
        __syncthreads();
    }
    #pragma unroll
    for (int i = 0; i < 4; i++) {
        float4 o = {acc[i][0], acc[i][1], acc[i][2], acc[i][3]};
        *(float4*)(O + (size_t)(b * TGTL + qt * 64 + ty * 4 + i) * DMODEL + h * 64 + tx * 4) = o;
    }
}

// ---------------- fused residual + LayerNorm (x = LN(x + a)) ----------------
__global__ void ln_res(float* __restrict__ x, const float* __restrict__ a,
                       const float* __restrict__ g, const float* __restrict__ bb) {
    int row = blockIdx.x, tid = threadIdx.x;
    float* xr = x + (size_t)row * DMODEL;
    const float* ar = a + (size_t)row * DMODEL;
    float v[4];
    float s = 0.f;
    #pragma unroll
    for (int u = 0; u < 4; u++) {
        int i = tid + u * 256;
        v[u] = xr[i] + ar[i];
        s += v[u];
    }
    s = blkReduceSum(s);
    float mu = s * (1.0f / DMODEL);
    float q = 0.f;
    #pragma unroll
    for (int u = 0; u < 4; u++) { float d = v[u] - mu; q += d * d; }
    q = blkReduceSum(q);
    float rs = rsqrtf(q * (1.0f / DMODEL) + 1e-5f);
    #pragma unroll
    for (int u = 0; u < 4; u++) {
        int i = tid + u * 256;
        xr[i] = (v[u] - mu) * rs * g[i] + bb[i];
    }
}

// ---------------- host orchestration ----------------------------------------
extern "C" void kernel_launch(void* const* d_in, const int* in_sizes, int n_in,
                              void* d_out, int out_size) {
    (void)n_in; (void)out_size;
    // input index mapping: detect dict order vs signature order via in_sizes[3]
    // dict: src,tgt,emb,fc_w,fc_b, [16 attn w/b], w1,b1,w2,b2, n1g,n2g,n3g,n1b,n2b,n3b
    // sig : src,tgt,emb, [16 attn w/b], w1,b1,w2,b2, n1g,n1b,n2g,n2b,n3g,n3b, fc_w,fc_b
    int dict = (in_sizes[3] == 32768000);
    int base, iFCW, iFCB, iN1G, iN1B, iN2G, iN2B, iN3G, iN3B;
    if (dict) {
        iFCW = 3; iFCB = 4; base = 5;
        iN1G = base + 20; iN2G = base + 21; iN3G = base + 22;
        iN1B = base + 23; iN2B = base + 24; iN3B = base + 25;
    } else {
        base = 3; iFCW = 29; iFCB = 30;
        iN1G = base + 20; iN1B = base + 21; iN2G = base + 22;
        iN2B = base + 23; iN3G = base + 24; iN3B = base + 25;
    }
    const float* src  = (const float*)d_in[0];
    const int*   tgt  = (const int*)d_in[1];
    const float* emb  = (const float*)d_in[2];
    const float* fcw  = (const float*)d_in[iFCW];
    const float* fcb  = (const float*)d_in[iFCB];
    // attn params, same relative order in both layouts:
    // 0 sa_wq 1 sa_bq 2 sa_wk 3 sa_bk 4 sa_wv 5 sa_bv 6 sa_wo 7 sa_bo
    // 8 ca_wq ... 15 ca_bo
    const float* AP[16];
    for (int i = 0; i < 16; i++) AP[i] = (const float*)d_in[base + i];
    const float* w1 = (const float*)d_in[base + 16];
    const float* b1 = (const float*)d_in[base + 17];
    const float* w2 = (const float*)d_in[base + 18];
    const float* b2 = (const float*)d_in[base + 19];
    const float* n1g = (const float*)d_in[iN1G];
    const float* n1b = (const float*)d_in[iN1B];
    const float* n2g = (const float*)d_in[iN2G];
    const float* n2b = (const float*)d_in[iN2B];
    const float* n3g = (const float*)d_in[iN3G];
    const float* n3b = (const float*)d_in[iN3B];

    float *x, *enc, *q, *k, *v, *attn, *proj, *ffn, *sc;
    cudaGetSymbolAddress((void**)&x,    g_x);
    cudaGetSymbolAddress((void**)&enc,  g_enc);
    cudaGetSymbolAddress((void**)&q,    g_q);
    cudaGetSymbolAddress((void**)&k,    g_k);
    cudaGetSymbolAddress((void**)&v,    g_v);
    cudaGetSymbolAddress((void**)&attn, g_attn);
    cudaGetSymbolAddress((void**)&proj, g_proj);
    cudaGetSymbolAddress((void**)&ffn,  g_ffn);
    cudaGetSymbolAddress((void**)&sc,   g_sc);

    encpe_kernel<<<NE, 256>>>(src, enc);
    embed_kernel<<<NQ, 256>>>(tgt, emb, x);

    dim3 gDD(DMODEL / 64, NQ / 64);        // [2048,1024] out
    dim3 gED(DMODEL / 64, NE / 64);        // [1024,1024] out
    dim3 gFF(DFF / 64, NQ / 64);           // [2048,4096] out
    int nSMrows = Bsz * NHEAD * TGTL;      // softmax rows

    for (int l = 0; l < NLAYER; l++) {
        size_t ow = (size_t)l * DMODEL * DMODEL, ob = (size_t)l * DMODEL;
        size_t ow1 = (size_t)l * DMODEL * DFF, ob1 = (size_t)l * DFF;

        // ---- self attention ----
        sgemm<<<gDD, 256>>>(x, AP[0] + ow, AP[1] + ob, q, NQ, DMODEL, DMODEL, 0);
        sgemm<<<gDD, 256>>>(x, AP[2] + ow, AP[3] + ob, k, NQ, DMODEL, DMODEL, 0);
        sgemm<<<gDD, 256>>>(x, AP[4] + ow, AP[5] + ob, v, NQ, DMODEL, DMODEL, 0);
        attn_scores<<<dim3(8 * 8, NHEAD, Bsz), 256>>>(q, k, sc, TGTL, 1, tgt);
        softmax_rows<<<nSMrows, 256>>>(sc, TGTL);
        attn_pv<<<dim3(8, NHEAD, Bsz), 256>>>(sc, v, attn, TGTL);
        sgemm<<<gDD, 256>>>(attn, AP[6] + ow, AP[7] + ob, proj, NQ, DMODEL, DMODEL, 0);
        ln_res<<<NQ, 256>>>(x, proj, n1g + ob, n1b + ob);

        // ---- cross attention ----
        sgemm<<<gDD, 256>>>(x,   AP[8]  + ow, AP[9]  + ob, q, NQ, DMODEL, DMODEL, 0);
        sgemm<<<gED, 256>>>(enc, AP[10] + ow, AP[11] + ob, k, NE, DMODEL, DMODEL, 0);
        sgemm<<<gED, 256>>>(enc, AP[12] + ow, AP[13] + ob, v, NE, DMODEL, DMODEL, 0);
        attn_scores<<<dim3(8 * 4, NHEAD, Bsz), 256>>>(q, k, sc, SRCL, 0, tgt);
        softmax_rows<<<nSMrows, 256>>>(sc, SRCL);
        attn_pv<<<dim3(8, NHEAD, Bsz), 256>>>(sc, v, attn, SRCL);
        sgemm<<<gDD, 256>>>(attn, AP[14] + ow, AP[15] + ob, proj, NQ, DMODEL, DMODEL, 0);
        ln_res<<<NQ, 256>>>(x, proj, n2g + ob, n2b + ob);

        // ---- feed forward ----
        sgemm<<<gFF, 256>>>(x, w1 + ow1, b1 + ob1, ffn, NQ, DFF, DMODEL, 1);
        sgemm<<<gDD, 256>>>(ffn, w2 + ow1, b2 + ob, proj, NQ, DMODEL, DFF, 0);
        ln_res<<<NQ, 256>>>(x, proj, n3g + ob, n3b + ob);
    }

    // ---- final projection to vocab ----
    sgemm<<<dim3(VOC / 64, NQ / 64), 256>>>(x, fcw, fcb, (float*)d_out,
                                            NQ, VOC, DMODEL, 0);
}

// round 3
// speedup vs baseline: 2.2997x; 2.2997x over previous
#include <cuda_runtime.h>
#include <math.h>
#include <stdint.h>

#define Bsz 4
#define SRCL 256
#define TGTL 512
#define DMODEL 1024
#define NHEAD 16
#define DKH 64
#define NLAYER 8
#define DFF 4096
#define VOC 32000
#define NQ (Bsz*TGTL)   // 2048 decoder token rows
#define NE (Bsz*SRCL)   // 1024 encoder token rows

// ---------------- scratch (device globals; no allocations allowed) ----------
__device__ float g_x[NQ*DMODEL];
__device__ float g_enc[NE*DMODEL];
__device__ float g_q[NQ*DMODEL];
__device__ float g_k[NQ*DMODEL];
__device__ float g_v[NQ*DMODEL];
__device__ float g_attn[NQ*DMODEL];
__device__ float g_proj[NQ*DMODEL];
__device__ float g_ffn[NQ*DFF];
__device__ float g_sc[(size_t)Bsz*NHEAD*TGTL*TGTL];

// ---------------- helpers ---------------------------------------------------
__device__ __forceinline__ float blkReduceSum(float v) {
    #pragma unroll
    for (int o = 16; o > 0; o >>= 1) v += __shfl_xor_sync(0xffffffffu, v, o);
    __shared__ float sm[8];
    int w = threadIdx.x >> 5, ln = threadIdx.x & 31;
    __syncthreads();
    if (ln == 0) sm[w] = v;
    __syncthreads();
    float r = sm[0];
    #pragma unroll
    for (int i = 1; i < 8; i++) r += sm[i];
    return r;
}

__device__ __forceinline__ float blkReduceMax(float v) {
    #pragma unroll
    for (int o = 16; o > 0; o >>= 1) v = fmaxf(v, __shfl_xor_sync(0xffffffffu, v, o));
    __shared__ float sm[8];
    int w = threadIdx.x >> 5, ln = threadIdx.x & 31;
    __syncthreads();
    if (ln == 0) sm[w] = v;
    __syncthreads();
    float r = sm[0];
    #pragma unroll
    for (int i = 1; i < 8; i++) r = fmaxf(r, sm[i]);
    return r;
}

__device__ __forceinline__ uint32_t f2tf32(float f) {
    uint32_t u;
    asm("cvt.rna.tf32.f32 %0, %1;" : "=r"(u) : "f"(f));
    return u;
}

// positional encoding value for (pos, dim)
__device__ __forceinline__ float pe_val(int pos, int d) {
    float div = expf((float)(d & ~1) * (-9.210340371976184f / 1024.0f));
    float ang = (float)pos * div;
    return (d & 1) ? cosf(ang) : sinf(ang);
}

// ---------------- embedding / encoder PE ------------------------------------
__global__ void embed_kernel(const int* __restrict__ tgt,
                             const float* __restrict__ emb,
                             float* __restrict__ x) {
    int row = blockIdx.x;
    int t = row % TGTL;
    int tok = tgt[row];
    const float* er = emb + (size_t)tok * DMODEL;
    float* xr = x + (size_t)row * DMODEL;
    for (int d = threadIdx.x; d < DMODEL; d += blockDim.x)
        xr[d] = er[d] + pe_val(t, d);
}

__global__ void encpe_kernel(const float* __restrict__ src,
                             float* __restrict__ enc) {
    int row = blockIdx.x;
    int s = row % SRCL;
    const float* sr = src + (size_t)row * DMODEL;
    float* er = enc + (size_t)row * DMODEL;
    for (int d = threadIdx.x; d < DMODEL; d += blockDim.x)
        er[d] = sr[d] + pe_val(s, d);
}

// ---------------- TF32 tensor-core GEMM -------------------------------------
// C[M,N] = A[M,K]@W[K,N] + bias, optional relu.
// 128x128 block tile, BK=16, 256 threads = 8 warps, each warp 64x32.
// mma.sync.aligned.m16n8k8.row.col.f32.tf32.tf32.f32
// Smem stride padded to 136 floats -> fragment reads bank-conflict-free.
#define BMt 128
#define BNt 128
#define BKt 16
#define LDT 136

__global__ void __launch_bounds__(256, 2)
gemm_tf32(const float* __restrict__ A, const float* __restrict__ W,
          const float* __restrict__ bias, float* __restrict__ C,
          int M, int N, int K, int relu) {
    __shared__ uint32_t As[BKt][LDT];
    __shared__ uint32_t Bs[BKt][LDT];

    int tid = threadIdx.x;
    int warp = tid >> 5, lane = tid & 31;
    int g = lane >> 2, c = lane & 3;           // groupID, threadID_in_group
    int wm = (warp & 1) * 64, wn = (warp >> 1) * 32;
    int m0 = blockIdx.y * BMt, n0 = blockIdx.x * BNt;

    // A staging: thread -> row am (2 threads per row), 8 k's each
    int am = tid >> 1, akg = (tid & 1) * 8;
    const float* Ap = A + (size_t)(m0 + am) * K + akg;
    // B staging: thread -> k row bk (16 threads per row), two float4 per thread
    int bk = tid >> 4, bn = (tid & 15) * 4;
    const float* Wp = W + (size_t)bk * N + n0 + bn;

    float acc[4][4][4];
    #pragma unroll
    for (int i = 0; i < 4; i++)
        #pragma unroll
        for (int j = 0; j < 4; j++)
            #pragma unroll
            for (int r = 0; r < 4; r++) acc[i][j][r] = 0.f;

    // prefetch tile 0
    float4 ra0 = *(const float4*)(Ap);
    float4 ra1 = *(const float4*)(Ap + 4);
    float4 rb0 = *(const float4*)(Wp);
    float4 rb1 = *(const float4*)(Wp + 64);

    for (int k0 = 0; k0 < K; k0 += BKt) {
        __syncthreads();
        // store (with tf32 convert); As transposed to [k][m]
        As[akg + 0][am] = f2tf32(ra0.x);
        As[akg + 1][am] = f2tf32(ra0.y);
        As[akg + 2][am] = f2tf32(ra0.z);
        As[akg + 3][am] = f2tf32(ra0.w);
        As[akg + 4][am] = f2tf32(ra1.x);
        As[akg + 5][am] = f2tf32(ra1.y);
        As[akg + 6][am] = f2tf32(ra1.z);
        As[akg + 7][am] = f2tf32(ra1.w);
        Bs[bk][bn + 0] = f2tf32(rb0.x);
        Bs[bk][bn + 1] = f2tf32(rb0.y);
        Bs[bk][bn + 2] = f2tf32(rb0.z);
        Bs[bk][bn + 3] = f2tf32(rb0.w);
        Bs[bk][bn + 64] = f2tf32(rb1.x);
        Bs[bk][bn + 65] = f2tf32(rb1.y);
        Bs[bk][bn + 66] = f2tf32(rb1.z);
        Bs[bk][bn + 67] = f2tf32(rb1.w);
        __syncthreads();

        // prefetch next tile while computing this one
        if (k0 + BKt < K) {
            ra0 = *(const float4*)(Ap + k0 + BKt);
            ra1 = *(const float4*)(Ap + k0 + BKt + 4);
            rb0 = *(const float4*)(Wp + (size_t)(k0 + BKt) * N);
            rb1 = *(const float4*)(Wp + (size_t)(k0 + BKt) * N + 64);
        }

        #pragma unroll
        for (int ks = 0; ks < 2; ks++) {
            int kb = ks * 8;
            uint32_t af[4][4], bf[4][2];
            #pragma unroll
            for (int im = 0; im < 4; im++) {
                int m = wm + im * 16;
                af[im][0] = As[kb + c][m + g];
                af[im][1] = As[kb + c][m + g + 8];
                af[im][2] = As[kb + c + 4][m + g];
                af[im][3] = As[kb + c + 4][m + g + 8];
            }
            #pragma unroll
            for (int jn = 0; jn < 4; jn++) {
                int n = wn + jn * 8;
                bf[jn][0] = Bs[kb + c][n + g];
                bf[jn][1] = Bs[kb + c + 4][n + g];
            }
            #pragma unroll
            for (int im = 0; im < 4; im++)
                #pragma unroll
                for (int jn = 0; jn < 4; jn++) {
                    asm volatile(
                        "mma.sync.aligned.m16n8k8.row.col.f32.tf32.tf32.f32 "
                        "{%0,%1,%2,%3},{%4,%5,%6,%7},{%8,%9},{%0,%1,%2,%3};"
                        : "+f"(acc[im][jn][0]), "+f"(acc[im][jn][1]),
                          "+f"(acc[im][jn][2]), "+f"(acc[im][jn][3])
                        : "r"(af[im][0]), "r"(af[im][1]),
                          "r"(af[im][2]), "r"(af[im][3]),
                          "r"(bf[jn][0]), "r"(bf[jn][1]));
                }
        }
    }

    // epilogue: bias (+relu), float2 stores
    #pragma unroll
    for (int jn = 0; jn < 4; jn++) {
        int col = n0 + wn + jn * 8 + 2 * c;
        float b0v = __ldg(bias + col), b1v = __ldg(bias + col + 1);
        #pragma unroll
        for (int im = 0; im < 4; im++) {
            int row0 = m0 + wm + im * 16 + g;
            float v0 = acc[im][jn][0] + b0v;
            float v1 = acc[im][jn][1] + b1v;
            float v2 = acc[im][jn][2] + b0v;
            float v3 = acc[im][jn][3] + b1v;
            if (relu) {
                v0 = fmaxf(v0, 0.f); v1 = fmaxf(v1, 0.f);
                v2 = fmaxf(v2, 0.f); v3 = fmaxf(v3, 0.f);
            }
            *(float2*)(C + (size_t)row0 * N + col)       = make_float2(v0, v1);
            *(float2*)(C + (size_t)(row0 + 8) * N + col) = make_float2(v2, v3);
        }
    }
}

// ---------------- attention scores: S = Q K^T / 8 (+mask) -------------------
__global__ void attn_scores(const float* __restrict__ Q, const float* __restrict__ Kp,
                            float* __restrict__ S, int Sk, int causal,
                            const int* __restrict__ tgt) {
    int tk = Sk >> 6;
    int qt = blockIdx.x / tk, kt = blockIdx.x % tk;
    int h = blockIdx.y, b = blockIdx.z;
    __shared__ float Qs[64][64];
    __shared__ float Ks[64][64];
    int tid = threadIdx.x;
    int tx = tid & 15, ty = tid >> 4;
    int r = tid >> 2, cg = tid & 3;

    const float* qbase = Q + (size_t)(b * TGTL + qt * 64 + r) * DMODEL + h * 64 + cg * 16;
    const float* kbase = Kp + (size_t)(b * Sk + kt * 64 + r) * DMODEL + h * 64 + cg * 16;
    #pragma unroll
    for (int u = 0; u < 4; u++) {
        float4 a = *(const float4*)(qbase + u * 4);
        int c = cg * 16 + u * 4;
        Qs[c + 0][r] = a.x; Qs[c + 1][r] = a.y; Qs[c + 2][r] = a.z; Qs[c + 3][r] = a.w;
        float4 kk = *(const float4*)(kbase + u * 4);
        Ks[c + 0][r] = kk.x; Ks[c + 1][r] = kk.y; Ks[c + 2][r] = kk.z; Ks[c + 3][r] = kk.w;
    }
    __syncthreads();

    float acc[4][4] = {};
    #pragma unroll
    for (int d = 0; d < 64; d++) {
        float4 av = *(const float4*)&Qs[d][ty * 4];
        float4 bv = *(const float4*)&Ks[d][tx * 4];
        float ar[4] = {av.x, av.y, av.z, av.w};
        float br[4] = {bv.x, bv.y, bv.z, bv.w};
        #pragma unroll
        for (int i = 0; i < 4; i++)
            #pragma unroll
            for (int j = 0; j < 4; j++)
                acc[i][j] = fmaf(ar[i], br[j], acc[i][j]);
    }

    float* srow = S + ((size_t)(b * NHEAD + h) * TGTL) * Sk;
    #pragma unroll
    for (int i = 0; i < 4; i++) {
        int gi = qt * 64 + ty * 4 + i;
        int rowok = 1;
        if (causal) rowok = (tgt[b * TGTL + gi] != 0);
        #pragma unroll
        for (int j = 0; j < 4; j++) {
            int gj = kt * 64 + tx * 4 + j;
            float v = acc[i][j] * 0.125f;
            if (causal && (gj > gi || !rowok)) v = -1e9f;
            srow[(size_t)gi * Sk + gj] = v;
        }
    }
}

// ---------------- row softmax (in place) ------------------------------------
__global__ void softmax_rows(float* __restrict__ S, int Sk) {
    float* row = S + (size_t)blockIdx.x * Sk;
    int tid = threadIdx.x;
    float e[2];
    int n = Sk >> 8;
    float m = -3.4e38f;
    for (int u = 0; u < n; u++) m = fmaxf(m, row[tid + u * 256]);
    m = blkReduceMax(m);
    float s = 0.f;
    for (int u = 0; u < n; u++) { e[u] = expf(row[tid + u * 256] - m); s += e[u]; }
    s = blkReduceSum(s);
    float inv = 1.0f / s;
    for (int u = 0; u < n; u++) row[tid + u * 256] = e[u] * inv;
}

// ---------------- attention output: O = P @ V -------------------------------
__global__ void attn_pv(const float* __restrict__ P, const float* __restrict__ V,
                        float* __restrict__ O, int Sk) {
    int qt = blockIdx.x, h = blockIdx.y, b = blockIdx.z;
    __shared__ float Ps[64][64];
    __shared__ float Vs[64][64];
    int tid = threadIdx.x;
    int tx = tid & 15, ty = tid >> 4;
    int r = tid >> 2, cg = tid & 3;

    const float* pbase = P + ((size_t)(b * NHEAD + h) * TGTL + qt * 64 + r) * Sk;
    float acc[4][4] = {};
    for (int kc = 0; kc < Sk; kc += 64) {
        #pragma unroll
        for (int u = 0; u < 4; u++) {
            int c = cg * 16 + u * 4;
            float4 p = *(const float4*)(pbase + kc + c);
            Ps[c + 0][r] = p.x; Ps[c + 1][r] = p.y; Ps[c + 2][r] = p.z; Ps[c + 3][r] = p.w;
            float4 vv = *(const float4*)(V + (size_t)(b * Sk + kc + r) * DMODEL + h * 64 + c);
            *(float4*)&Vs[r][c] = vv;
        }
        __syncthreads();
        #pragma unroll
        for (int j = 0; j < 64; j++) {
            float4 av = *(const float4*)&Ps[j][ty * 4];
            float4 bv = *(const float4*)&Vs[j][tx * 4];
            float ar[4] = {av.x, av.y, av.z, av.w};
            float br[4] = {bv.x, bv.y, bv.z, bv.w};
            #pragma unroll
            for (int i = 0; i < 4; i++)
                #pragma unroll
                for (int jj = 0; jj < 4; jj++)
                    acc[i][jj] = fmaf(ar[i], br[jj], acc[i][jj]);
        }
        __syncthreads();
    }
    #pragma unroll
    for (int i = 0; i < 4; i++) {
        float4 o = {acc[i][0], acc[i][1], acc[i][2], acc[i][3]};
        *(float4*)(O + (size_t)(b * TGTL + qt * 64 + ty * 4 + i) * DMODEL + h * 64 + tx * 4) = o;
    }
}

// ---------------- fused residual + LayerNorm (x = LN(x + a)) ----------------
__global__ void ln_res(float* __restrict__ x, const float* __restrict__ a,
                       const float* __restrict__ g, const float* __restrict__ bb) {
    int row = blockIdx.x, tid = threadIdx.x;
    float* xr = x + (size_t)row * DMODEL;
    const float* ar = a + (size_t)row * DMODEL;
    float v[4];
    float s = 0.f;
    #pragma unroll
    for (int u = 0; u < 4; u++) {
        int i = tid + u * 256;
        v[u] = xr[i] + ar[i];
        s += v[u];
    }
    s = blkReduceSum(s);
    float mu = s * (1.0f / DMODEL);
    float q = 0.f;
    #pragma unroll
    for (int u = 0; u < 4; u++) { float d = v[u] - mu; q += d * d; }
    q = blkReduceSum(q);
    float rs = rsqrtf(q * (1.0f / DMODEL) + 1e-5f);
    #pragma unroll
    for (int u = 0; u < 4; u++) {
        int i = tid + u * 256;
        xr[i] = (v[u] - mu) * rs * g[i] + bb[i];
    }
}

// ---------------- host orchestration ----------------------------------------
extern "C" void kernel_launch(void* const* d_in, const int* in_sizes, int n_in,
                              void* d_out, int out_size) {
    (void)n_in; (void)out_size;
    int dict = (in_sizes[3] == 32768000);
    int base, iFCW, iFCB, iN1G, iN1B, iN2G, iN2B, iN3G, iN3B;
    if (dict) {
        iFCW = 3; iFCB = 4; base = 5;
        iN1G = base + 20; iN2G = base + 21; iN3G = base + 22;
        iN1B = base + 23; iN2B = base + 24; iN3B = base + 25;
    } else {
        base = 3; iFCW = 29; iFCB = 30;
        iN1G = base + 20; iN1B = base + 21; iN2G = base + 22;
        iN2B = base + 23; iN3G = base + 24; iN3B = base + 25;
    }
    const float* src  = (const float*)d_in[0];
    const int*   tgt  = (const int*)d_in[1];
    const float* emb  = (const float*)d_in[2];
    const float* fcw  = (const float*)d_in[iFCW];
    const float* fcb  = (const float*)d_in[iFCB];
    const float* AP[16];
    for (int i = 0; i < 16; i++) AP[i] = (const float*)d_in[base + i];
    const float* w1 = (const float*)d_in[base + 16];
    const float* b1 = (const float*)d_in[base + 17];
    const float* w2 = (const float*)d_in[base + 18];
    const float* b2 = (const float*)d_in[base + 19];
    const float* n1g = (const float*)d_in[iN1G];
    const float* n1b = (const float*)d_in[iN1B];
    const float* n2g = (const float*)d_in[iN2G];
    const float* n2b = (const float*)d_in[iN2B];
    const float* n3g = (const float*)d_in[iN3G];
    const float* n3b = (const float*)d_in[iN3B];

    float *x, *enc, *q, *k, *v, *attn, *proj, *ffn, *sc;
    cudaGetSymbolAddress((void**)&x,    g_x);
    cudaGetSymbolAddress((void**)&enc,  g_enc);
    cudaGetSymbolAddress((void**)&q,    g_q);
    cudaGetSymbolAddress((void**)&k,    g_k);
    cudaGetSymbolAddress((void**)&v,    g_v);
    cudaGetSymbolAddress((void**)&attn, g_attn);
    cudaGetSymbolAddress((void**)&proj, g_proj);
    cudaGetSymbolAddress((void**)&ffn,  g_ffn);
    cudaGetSymbolAddress((void**)&sc,   g_sc);

    encpe_kernel<<<NE, 256>>>(src, enc);
    embed_kernel<<<NQ, 256>>>(tgt, emb, x);

    dim3 gDD(DMODEL / BNt, NQ / BMt);      // 2048x1024
    dim3 gED(DMODEL / BNt, NE / BMt);      // 1024x1024
    dim3 gFF(DFF / BNt, NQ / BMt);         // 2048x4096
    int nSMrows = Bsz * NHEAD * TGTL;

    for (int l = 0; l < NLAYER; l++) {
        size_t ow = (size_t)l * DMODEL * DMODEL, ob = (size_t)l * DMODEL;
        size_t ow1 = (size_t)l * DMODEL * DFF, ob1 = (size_t)l * DFF;

        // ---- self attention ----
        gemm_tf32<<<gDD, 256>>>(x, AP[0] + ow, AP[1] + ob, q, NQ, DMODEL, DMODEL, 0);
        gemm_tf32<<<gDD, 256>>>(x, AP[2] + ow, AP[3] + ob, k, NQ, DMODEL, DMODEL, 0);
        gemm_tf32<<<gDD, 256>>>(x, AP[4] + ow, AP[5] + ob, v, NQ, DMODEL, DMODEL, 0);
        attn_scores<<<dim3(8 * 8, NHEAD, Bsz), 256>>>(q, k, sc, TGTL, 1, tgt);
        softmax_rows<<<nSMrows, 256>>>(sc, TGTL);
        attn_pv<<<dim3(8, NHEAD, Bsz), 256>>>(sc, v, attn, TGTL);
        gemm_tf32<<<gDD, 256>>>(attn, AP[6] + ow, AP[7] + ob, proj, NQ, DMODEL, DMODEL, 0);
        ln_res<<<NQ, 256>>>(x, proj, n1g + ob, n1b + ob);

        // ---- cross attention ----
        gemm_tf32<<<gDD, 256>>>(x,   AP[8]  + ow, AP[9]  + ob, q, NQ, DMODEL, DMODEL, 0);
        gemm_tf32<<<gED, 256>>>(enc, AP[10] + ow, AP[11] + ob, k, NE, DMODEL, DMODEL, 0);
        gemm_tf32<<<gED, 256>>>(enc, AP[12] + ow, AP[13] + ob, v, NE, DMODEL, DMODEL, 0);
        attn_scores<<<dim3(8 * 4, NHEAD, Bsz), 256>>>(q, k, sc, SRCL, 0, tgt);
        softmax_rows<<<nSMrows, 256>>>(sc, SRCL);
        attn_pv<<<dim3(8, NHEAD, Bsz), 256>>>(sc, v, attn, SRCL);
        gemm_tf32<<<gDD, 256>>>(attn, AP[14] + ow, AP[15] + ob, proj, NQ, DMODEL, DMODEL, 0);
        ln_res<<<NQ, 256>>>(x, proj, n2g + ob, n2b + ob);

        // ---- feed forward ----
        gemm_tf32<<<gFF, 256>>>(x, w1 + ow1, b1 + ob1, ffn, NQ, DFF, DMODEL, 1);
        gemm_tf32<<<gDD, 256>>>(ffn, w2 + ow1, b2 + ob, proj, NQ, DMODEL, DFF, 0);
        ln_res<<<NQ, 256>>>(x, proj, n3g + ob, n3b + ob);
    }

    // ---- final projection to vocab ----
    gemm_tf32<<<dim3(VOC / BNt, NQ / BMt), 256>>>(x, fcw, fcb, (float*)d_out,
                                                  NQ, VOC, DMODEL, 0);
}

// round 5
// speedup vs baseline: 2.4979x; 1.0862x over previous
#include <cuda_runtime.h>
#include <math.h>
#include <stdint.h>

#define Bsz 4
#define SRCL 256
#define TGTL 512
#define DMODEL 1024
#define NHEAD 16
#define DKH 64
#define NLAYER 8
#define DFF 4096
#define VOC 32000
#define NQ (Bsz*TGTL)
#define NE (Bsz*SRCL)

// ---------------- scratch (device globals; no allocations allowed) ----------
__device__ float g_x[NQ*DMODEL];
__device__ float g_enc[NE*DMODEL];
__device__ float g_q[NQ*DMODEL];
__device__ float g_k[NQ*DMODEL];
__device__ float g_v[NQ*DMODEL];
__device__ float g_attn[NQ*DMODEL];
__device__ float g_proj[NQ*DMODEL];
__device__ float g_ffn[NQ*DFF];
__device__ float g_sc[(size_t)Bsz*NHEAD*TGTL*TGTL];

// ---------------- helpers ---------------------------------------------------
__device__ __forceinline__ float blkReduceSum(float v) {
    #pragma unroll
    for (int o = 16; o > 0; o >>= 1) v += __shfl_xor_sync(0xffffffffu, v, o);
    __shared__ float sm[8];
    int w = threadIdx.x >> 5, ln = threadIdx.x & 31;
    __syncthreads();
    if (ln == 0) sm[w] = v;
    __syncthreads();
    float r = sm[0];
    #pragma unroll
    for (int i = 1; i < 8; i++) r += sm[i];
    return r;
}

__device__ __forceinline__ float blkReduceMax(float v) {
    #pragma unroll
    for (int o = 16; o > 0; o >>= 1) v = fmaxf(v, __shfl_xor_sync(0xffffffffu, v, o));
    __shared__ float sm[8];
    int w = threadIdx.x >> 5, ln = threadIdx.x & 31;
    __syncthreads();
    if (ln == 0) sm[w] = v;
    __syncthreads();
    float r = sm[0];
    #pragma unroll
    for (int i = 1; i < 8; i++) r = fmaxf(r, sm[i]);
    return r;
}

__device__ __forceinline__ uint32_t f2tf32(float f) {
    uint32_t u;
    asm("cvt.rna.tf32.f32 %0, %1;" : "=r"(u) : "f"(f));
    return u;
}

#define MMA_TF32(ACC, A0, A1, A2, A3, B0, B1)                                  \
    asm volatile(                                                              \
        "mma.sync.aligned.m16n8k8.row.col.f32.tf32.tf32.f32 "                  \
        "{%0,%1,%2,%3},{%4,%5,%6,%7},{%8,%9},{%0,%1,%2,%3};"                   \
        : "+f"((ACC)[0]), "+f"((ACC)[1]), "+f"((ACC)[2]), "+f"((ACC)[3])       \
        : "r"(A0), "r"(A1), "r"(A2), "r"(A3), "r"(B0), "r"(B1))

__device__ __forceinline__ float pe_val(int pos, int d) {
    float div = expf((float)(d & ~1) * (-9.210340371976184f / 1024.0f));
    float ang = (float)pos * div;
    return (d & 1) ? cosf(ang) : sinf(ang);
}

// ---------------- embedding / encoder PE ------------------------------------
__global__ void embed_kernel(const int* __restrict__ tgt,
                             const float* __restrict__ emb,
                             float* __restrict__ x) {
    int row = blockIdx.x;
    int t = row % TGTL;
    int tok = tgt[row];
    const float* er = emb + (size_t)tok * DMODEL;
    float* xr = x + (size_t)row * DMODEL;
    for (int d = threadIdx.x; d < DMODEL; d += blockDim.x)
        xr[d] = er[d] + pe_val(t, d);
}

__global__ void encpe_kernel(const float* __restrict__ src,
                             float* __restrict__ enc) {
    int row = blockIdx.x;
    int s = row % SRCL;
    const float* sr = src + (size_t)row * DMODEL;
    float* er = enc + (size_t)row * DMODEL;
    for (int d = threadIdx.x; d < DMODEL; d += blockDim.x)
        er[d] = sr[d] + pe_val(s, d);
}

// ---------------- TF32 tensor-core GEMM (pipelined, z-batched) ---------------
// C[M,N] = A[M,K]@W[K,N] + bias, optional relu. blockIdx.z selects W/bias/C.
#define BMt 128
#define BNt 128
#define BKt 16
#define LDT 136

struct Tri {
    const float* W[3];
    const float* B[3];
    float* C[3];
};

__global__ void __launch_bounds__(256, 2)
gemm_tf32(const float* __restrict__ A, Tri t3, int M, int N, int K, int relu) {
    const float* __restrict__ W = t3.W[blockIdx.z];
    const float* __restrict__ bias = t3.B[blockIdx.z];
    float* __restrict__ C = t3.C[blockIdx.z];

    __shared__ uint32_t As[2][BKt][LDT];
    __shared__ uint32_t Bs[2][BKt][LDT];

    int tid = threadIdx.x;
    int warp = tid >> 5, lane = tid & 31;
    int g = lane >> 2, c = lane & 3;
    int wm = (warp & 1) * 64, wn = (warp >> 1) * 32;
    int m0 = blockIdx.y * BMt, n0 = blockIdx.x * BNt;

    int am = tid >> 1, akg = (tid & 1) * 8;
    const float* Ap = A + (size_t)(m0 + am) * K + akg;
    int bk = tid >> 4, bn = (tid & 15) * 4;
    const float* Wp = W + (size_t)bk * N + n0 + bn;

    float acc[4][4][4] = {};

    float4 ra0, ra1, rb0, rb1;
    ra0 = *(const float4*)(Ap);
    ra1 = *(const float4*)(Ap + 4);
    rb0 = *(const float4*)(Wp);
    rb1 = *(const float4*)(Wp + 64);

#define STORE_STAGE(S)                                                         \
    do {                                                                       \
        As[S][akg + 0][am] = f2tf32(ra0.x);                                    \
        As[S][akg + 1][am] = f2tf32(ra0.y);                                    \
        As[S][akg + 2][am] = f2tf32(ra0.z);                                    \
        As[S][akg + 3][am] = f2tf32(ra0.w);                                    \
        As[S][akg + 4][am] = f2tf32(ra1.x);                                    \
        As[S][akg + 5][am] = f2tf32(ra1.y);                                    \
        As[S][akg + 6][am] = f2tf32(ra1.z);                                    \
        As[S][akg + 7][am] = f2tf32(ra1.w);                                    \
        Bs[S][bk][bn + 0] = f2tf32(rb0.x);                                     \
        Bs[S][bk][bn + 1] = f2tf32(rb0.y);                                     \
        Bs[S][bk][bn + 2] = f2tf32(rb0.z);                                     \
        Bs[S][bk][bn + 3] = f2tf32(rb0.w);                                     \
        Bs[S][bk][bn + 64] = f2tf32(rb1.x);                                    \
        Bs[S][bk][bn + 65] = f2tf32(rb1.y);                                    \
        Bs[S][bk][bn + 66] = f2tf32(rb1.z);                                    \
        Bs[S][bk][bn + 67] = f2tf32(rb1.w);                                    \
    } while (0)

    STORE_STAGE(0);
    int T = K / BKt;
    for (int t = 0; t < T; t++) {
        __syncthreads();
        int s = t & 1;
        bool more = (t + 1 < T);
        if (more) {
            int k0 = (t + 1) * BKt;
            ra0 = *(const float4*)(Ap + k0);
            ra1 = *(const float4*)(Ap + k0 + 4);
            rb0 = *(const float4*)(Wp + (size_t)k0 * N);
            rb1 = *(const float4*)(Wp + (size_t)k0 * N + 64);
        }
        #pragma unroll
        for (int ks = 0; ks < 2; ks++) {
            int kb = ks * 8;
            uint32_t af[4][4], bf[4][2];
            #pragma unroll
            for (int im = 0; im < 4; im++) {
                int m = wm + im * 16;
                af[im][0] = As[s][kb + c][m + g];
                af[im][1] = As[s][kb + c][m + g + 8];
                af[im][2] = As[s][kb + c + 4][m + g];
                af[im][3] = As[s][kb + c + 4][m + g + 8];
            }
            #pragma unroll
            for (int jn = 0; jn < 4; jn++) {
                int n = wn + jn * 8;
                bf[jn][0] = Bs[s][kb + c][n + g];
                bf[jn][1] = Bs[s][kb + c + 4][n + g];
            }
            #pragma unroll
            for (int im = 0; im < 4; im++)
                #pragma unroll
                for (int jn = 0; jn < 4; jn++)
                    MMA_TF32(acc[im][jn], af[im][0], af[im][1], af[im][2],
                             af[im][3], bf[jn][0], bf[jn][1]);
        }
        if (more) STORE_STAGE(s ^ 1);
    }
#undef STORE_STAGE

    #pragma unroll
    for (int jn = 0; jn < 4; jn++) {
        int col = n0 + wn + jn * 8 + 2 * c;
        float b0v = __ldg(bias + col), b1v = __ldg(bias + col + 1);
        #pragma unroll
        for (int im = 0; im < 4; im++) {
            int row0 = m0 + wm + im * 16 + g;
            float v0 = acc[im][jn][0] + b0v;
            float v1 = acc[im][jn][1] + b1v;
            float v2 = acc[im][jn][2] + b0v;
            float v3 = acc[im][jn][3] + b1v;
            if (relu) {
                v0 = fmaxf(v0, 0.f); v1 = fmaxf(v1, 0.f);
                v2 = fmaxf(v2, 0.f); v3 = fmaxf(v3, 0.f);
            }
            *(float2*)(C + (size_t)row0 * N + col)       = make_float2(v0, v1);
            *(float2*)(C + (size_t)(row0 + 8) * N + col) = make_float2(v2, v3);
        }
    }
}

// ---------------- attention scores via TF32 MMA ------------------------------
// 64x64 output tile per block, 128 threads (4 warps, 16 rows each), dk=64.
__global__ void __launch_bounds__(128)
attn_scores_mma(const float* __restrict__ Q, const float* __restrict__ Kp,
                float* __restrict__ S, int Sk, int causal,
                const int* __restrict__ tgt) {
    int tk = Sk >> 6;
    int qt = blockIdx.x / tk, kt = blockIdx.x % tk;
    int h = blockIdx.y, b = blockIdx.z;
    __shared__ uint32_t Qs[64][68];   // [m][k]
    __shared__ uint32_t Ks[64][68];   // [n][k]

    int tid = threadIdx.x, warp = tid >> 5, lane = tid & 31;
    int g = lane >> 2, c = lane & 3;
    int row = tid >> 1, kg = (tid & 1) * 32;

    const float* qp = Q + (size_t)(b * TGTL + qt * 64 + row) * DMODEL + h * 64 + kg;
    const float* kp = Kp + (size_t)(b * Sk + kt * 64 + row) * DMODEL + h * 64 + kg;
    #pragma unroll
    for (int u = 0; u < 8; u++) {
        float4 qv = *(const float4*)(qp + u * 4);
        int cc = kg + u * 4;
        Qs[row][cc + 0] = f2tf32(qv.x); Qs[row][cc + 1] = f2tf32(qv.y);
        Qs[row][cc + 2] = f2tf32(qv.z); Qs[row][cc + 3] = f2tf32(qv.w);
        float4 kv = *(const float4*)(kp + u * 4);
        Ks[row][cc + 0] = f2tf32(kv.x); Ks[row][cc + 1] = f2tf32(kv.y);
        Ks[row][cc + 2] = f2tf32(kv.z); Ks[row][cc + 3] = f2tf32(kv.w);
    }
    __syncthreads();

    int mw = warp * 16;
    float acc[8][4] = {};
    #pragma unroll
    for (int kb = 0; kb < 64; kb += 8) {
        uint32_t a0 = Qs[mw + g][kb + c];
        uint32_t a1 = Qs[mw + g + 8][kb + c];
        uint32_t a2 = Qs[mw + g][kb + c + 4];
        uint32_t a3 = Qs[mw + g + 8][kb + c + 4];
        #pragma unroll
        for (int nb = 0; nb < 8; nb++) {
            uint32_t b0 = Ks[nb * 8 + g][kb + c];
            uint32_t b1 = Ks[nb * 8 + g][kb + c + 4];
            MMA_TF32(acc[nb], a0, a1, a2, a3, b0, b1);
        }
    }

    float* srow = S + ((size_t)(b * NHEAD + h) * TGTL) * Sk;
    int gi0 = qt * 64 + mw + g, gi1 = gi0 + 8;
    int ok0 = 1, ok1 = 1;
    if (causal) {
        ok0 = (tgt[b * TGTL + gi0] != 0);
        ok1 = (tgt[b * TGTL + gi1] != 0);
    }
    #pragma unroll
    for (int nb = 0; nb < 8; nb++) {
        int gj = kt * 64 + nb * 8 + 2 * c;
        float v0 = acc[nb][0] * 0.125f, v1 = acc[nb][1] * 0.125f;
        float v2 = acc[nb][2] * 0.125f, v3 = acc[nb][3] * 0.125f;
        if (causal) {
            if (gj > gi0 || !ok0) v0 = -1e9f;
            if (gj + 1 > gi0 || !ok0) v1 = -1e9f;
            if (gj > gi1 || !ok1) v2 = -1e9f;
            if (gj + 1 > gi1 || !ok1) v3 = -1e9f;
        }
        *(float2*)(srow + (size_t)gi0 * Sk + gj) = make_float2(v0, v1);
        *(float2*)(srow + (size_t)gi1 * Sk + gj) = make_float2(v2, v3);
    }
}

// ---------------- row softmax (in place) ------------------------------------
__global__ void softmax_rows(float* __restrict__ S, int Sk) {
    float* row = S + (size_t)blockIdx.x * Sk;
    int tid = threadIdx.x;
    float e[2];
    int n = Sk >> 8;
    float m = -3.4e38f;
    for (int u = 0; u < n; u++) m = fmaxf(m, row[tid + u * 256]);
    m = blkReduceMax(m);
    float s = 0.f;
    for (int u = 0; u < n; u++) { e[u] = expf(row[tid + u * 256] - m); s += e[u]; }
    s = blkReduceSum(s);
    float inv = 1.0f / s;
    for (int u = 0; u < n; u++) row[tid + u * 256] = e[u] * inv;
}

// ---------------- attention P@V via TF32 MMA ---------------------------------
__global__ void __launch_bounds__(128)
attn_pv_mma(const float* __restrict__ P, const float* __restrict__ V,
            float* __restrict__ O, int Sk) {
    int qt = blockIdx.x, h = blockIdx.y, b = blockIdx.z;
    __shared__ uint32_t Ps[64][68];   // [m][k]
    __shared__ uint32_t Vs[64][72];   // [k][n]

    int tid = threadIdx.x, warp = tid >> 5, lane = tid & 31;
    int g = lane >> 2, c = lane & 3;
    int row = tid >> 1, kg = (tid & 1) * 32;
    int mw = warp * 16;

    const float* pbase = P + ((size_t)(b * NHEAD + h) * TGTL + qt * 64 + row) * Sk + kg;
    float acc[8][4] = {};
    for (int kc = 0; kc < Sk; kc += 64) {
        #pragma unroll
        for (int u = 0; u < 8; u++) {
            float4 pv = *(const float4*)(pbase + kc + u * 4);
            int cc = kg + u * 4;
            Ps[row][cc + 0] = f2tf32(pv.x); Ps[row][cc + 1] = f2tf32(pv.y);
            Ps[row][cc + 2] = f2tf32(pv.z); Ps[row][cc + 3] = f2tf32(pv.w);
        }
        const float* vp = V + (size_t)(b * Sk + kc + row) * DMODEL + h * 64 + kg;
        #pragma unroll
        for (int u = 0; u < 8; u++) {
            float4 vv = *(const float4*)(vp + u * 4);
            int cc = kg + u * 4;
            Vs[row][cc + 0] = f2tf32(vv.x); Vs[row][cc + 1] = f2tf32(vv.y);
            Vs[row][cc + 2] = f2tf32(vv.z); Vs[row][cc + 3] = f2tf32(vv.w);
        }
        __syncthreads();
        #pragma unroll
        for (int kb = 0; kb < 64; kb += 8) {
            uint32_t a0 = Ps[mw + g][kb + c];
            uint32_t a1 = Ps[mw + g + 8][kb + c];
            uint32_t a2 = Ps[mw + g][kb + c + 4];
            uint32_t a3 = Ps[mw + g + 8][kb + c + 4];
            #pragma unroll
            for (int nb = 0; nb < 8; nb++) {
                uint32_t b0 = Vs[kb + c][nb * 8 + g];
                uint32_t b1 = Vs[kb + c + 4][nb * 8 + g];
                MMA_TF32(acc[nb], a0, a1, a2, a3, b0, b1);
            }
        }
        __syncthreads();
    }
    #pragma unroll
    for (int nb = 0; nb < 8; nb++) {
        int col = h * 64 + nb * 8 + 2 * c;
        size_t r0 = (size_t)(b * TGTL + qt * 64 + mw + g);
        *(float2*)(O + r0 * DMODEL + col)       = make_float2(acc[nb][0], acc[nb][1]);
        *(float2*)(O + (r0 + 8) * DMODEL + col) = make_float2(acc[nb][2], acc[nb][3]);
    }
}

// ---------------- fused residual + LayerNorm (x = LN(x + a)) ----------------
__global__ void ln_res(float* __restrict__ x, const float* __restrict__ a,
                       const float* __restrict__ g, const float* __restrict__ bb) {
    int row = blockIdx.x, tid = threadIdx.x;
    float* xr = x + (size_t)row * DMODEL;
    const float* ar = a + (size_t)row * DMODEL;
    float v[4];
    float s = 0.f;
    #pragma unroll
    for (int u = 0; u < 4; u++) {
        int i = tid + u * 256;
        v[u] = xr[i] + ar[i];
        s += v[u];
    }
    s = blkReduceSum(s);
    float mu = s * (1.0f / DMODEL);
    float q = 0.f;
    #pragma unroll
    for (int u = 0; u < 4; u++) { float d = v[u] - mu; q += d * d; }
    q = blkReduceSum(q);
    float rs = rsqrtf(q * (1.0f / DMODEL) + 1e-5f);
    #pragma unroll
    for (int u = 0; u < 4; u++) {
        int i = tid + u * 256;
        xr[i] = (v[u] - mu) * rs * g[i] + bb[i];
    }
}

// ---------------- host orchestration ----------------------------------------
static inline Tri tri1(const float* W, const float* B, float* C) {
    Tri t;
    for (int i = 0; i < 3; i++) { t.W[i] = W; t.B[i] = B; t.C[i] = C; }
    return t;
}

extern "C" void kernel_launch(void* const* d_in, const int* in_sizes, int n_in,
                              void* d_out, int out_size) {
    (void)n_in; (void)out_size;
    int dict = (in_sizes[3] == 32768000);
    int base, iFCW, iFCB, iN1G, iN1B, iN2G, iN2B, iN3G, iN3B;
    if (dict) {
        iFCW = 3; iFCB = 4; base = 5;
        iN1G = base + 20; iN2G = base + 21; iN3G = base + 22;
        iN1B = base + 23; iN2B = base + 24; iN3B = base + 25;
    } else {
        base = 3; iFCW = 29; iFCB = 30;
        iN1G = base + 20; iN1B = base + 21; iN2G = base + 22;
        iN2B = base + 23; iN3G = base + 24; iN3B = base + 25;
    }
    const float* src  = (const float*)d_in[0];
    const int*   tgt  = (const int*)d_in[1];
    const float* emb  = (const float*)d_in[2];
    const float* fcw  = (const float*)d_in[iFCW];
    const float* fcb  = (const float*)d_in[iFCB];
    const float* AP[16];
    for (int i = 0; i < 16; i++) AP[i] = (const float*)d_in[base + i];
    const float* w1 = (const float*)d_in[base + 16];
    const float* b1 = (const float*)d_in[base + 17];
    const float* w2 = (const float*)d_in[base + 18];
    const float* b2 = (const float*)d_in[base + 19];
    const float* n1g = (const float*)d_in[iN1G];
    const float* n1b = (const float*)d_in[iN1B];
    const float* n2g = (const float*)d_in[iN2G];
    const float* n2b = (const float*)d_in[iN2B];
    const float* n3g = (const float*)d_in[iN3G];
    const float* n3b = (const float*)d_in[iN3B];

    float *x, *enc, *q, *k, *v, *attn, *proj, *ffn, *sc;
    cudaGetSymbolAddress((void**)&x,    g_x);
    cudaGetSymbolAddress((void**)&enc,  g_enc);
    cudaGetSymbolAddress((void**)&q,    g_q);
    cudaGetSymbolAddress((void**)&k,    g_k);
    cudaGetSymbolAddress((void**)&v,    g_v);
    cudaGetSymbolAddress((void**)&attn, g_attn);
    cudaGetSymbolAddress((void**)&proj, g_proj);
    cudaGetSymbolAddress((void**)&ffn,  g_ffn);
    cudaGetSymbolAddress((void**)&sc,   g_sc);

    encpe_kernel<<<NE, 256>>>(src, enc);
    embed_kernel<<<NQ, 256>>>(tgt, emb, x);

    dim3 gDD(DMODEL / BNt, NQ / BMt, 1);
    dim3 gDD3(DMODEL / BNt, NQ / BMt, 3);
    dim3 gED2(DMODEL / BNt, NE / BMt, 2);
    dim3 gFF(DFF / BNt, NQ / BMt, 1);
    int nSMrows = Bsz * NHEAD * TGTL;

    for (int l = 0; l < NLAYER; l++) {
        size_t ow = (size_t)l * DMODEL * DMODEL, ob = (size_t)l * DMODEL;
        size_t ow1 = (size_t)l * DMODEL * DFF, ob1 = (size_t)l * DFF;

        // ---- self attention: batched QKV ----
        Tri qkv;
        qkv.W[0] = AP[0] + ow; qkv.B[0] = AP[1] + ob; qkv.C[0] = q;
        qkv.W[1] = AP[2] + ow; qkv.B[1] = AP[3] + ob; qkv.C[1] = k;
        qkv.W[2] = AP[4] + ow; qkv.B[2] = AP[5] + ob; qkv.C[2] = v;
        gemm_tf32<<<gDD3, 256>>>(x, qkv, NQ, DMODEL, DMODEL, 0);
        attn_scores_mma<<<dim3(8 * 8, NHEAD, Bsz), 128>>>(q, k, sc, TGTL, 1, tgt);
        softmax_rows<<<nSMrows, 256>>>(sc, TGTL);
        attn_pv_mma<<<dim3(8, NHEAD, Bsz), 128>>>(sc, v, attn, TGTL);
        gemm_tf32<<<gDD, 256>>>(attn, tri1(AP[6] + ow, AP[7] + ob, proj),
                                NQ, DMODEL, DMODEL, 0);
        ln_res<<<NQ, 256>>>(x, proj, n1g + ob, n1b + ob);

        // ---- cross attention: Q on x, batched KV on enc ----
        gemm_tf32<<<gDD, 256>>>(x, tri1(AP[8] + ow, AP[9] + ob, q),
                                NQ, DMODEL, DMODEL, 0);
        Tri ckv;
        ckv.W[0] = AP[10] + ow; ckv.B[0] = AP[11] + ob; ckv.C[0] = k;
        ckv.W[1] = AP[12] + ow; ckv.B[1] = AP[13] + ob; ckv.C[1] = v;
        ckv.W[2] = AP[10] + ow; ckv.B[2] = AP[11] + ob; ckv.C[2] = k;
        gemm_tf32<<<gED2, 256>>>(enc, ckv, NE, DMODEL, DMODEL, 0);
        attn_scores_mma<<<dim3(8 * 4, NHEAD, Bsz), 128>>>(q, k, sc, SRCL, 0, tgt);
        softmax_rows<<<nSMrows, 256>>>(sc, SRCL);
        attn_pv_mma<<<dim3(8, NHEAD, Bsz), 128>>>(sc, v, attn, SRCL);
        gemm_tf32<<<gDD, 256>>>(attn, tri1(AP[14] + ow, AP[15] + ob, proj),
                                NQ, DMODEL, DMODEL, 0);
        ln_res<<<NQ, 256>>>(x, proj, n2g + ob, n2b + ob);

        // ---- feed forward ----
        gemm_tf32<<<gFF, 256>>>(x, tri1(w1 + ow1, b1 + ob1, ffn),
                                NQ, DFF, DMODEL, 1);
        gemm_tf32<<<gDD, 256>>>(ffn, tri1(w2 + ow1, b2 + ob, proj),
                                NQ, DMODEL, DFF, 0);
        ln_res<<<NQ, 256>>>(x, proj, n3g + ob, n3b + ob);
    }

    // ---- final projection to vocab ----
    gemm_tf32<<<dim3(VOC / BNt, NQ / BMt, 1), 256>>>(
        x, tri1(fcw, fcb, (float*)d_out), NQ, VOC, DMODEL, 0);
}

// round 6
// speedup vs baseline: 2.9745x; 1.1908x over previous
#include <cuda_runtime.h>
#include <math.h>
#include <stdint.h>

#define Bsz 4
#define SRCL 256
#define TGTL 512
#define DMODEL 1024
#define NHEAD 16
#define DKH 64
#define NLAYER 8
#define DFF 4096
#define VOC 32000
#define NQ (Bsz*TGTL)
#define NE (Bsz*SRCL)

// ---------------- scratch (device globals; no allocations allowed) ----------
__device__ float g_x[NQ*DMODEL];
__device__ float g_enc[NE*DMODEL];
__device__ float g_q[NQ*DMODEL];
__device__ float g_k[NQ*DMODEL];
__device__ float g_v[NQ*DMODEL];
__device__ float g_attn[NQ*DMODEL];
__device__ float g_proj[NQ*DMODEL];
__device__ float g_ffn[NQ*DFF];

// ---------------- helpers ---------------------------------------------------
__device__ __forceinline__ float blkReduceSum(float v) {
    #pragma unroll
    for (int o = 16; o > 0; o >>= 1) v += __shfl_xor_sync(0xffffffffu, v, o);
    __shared__ float sm[8];
    int w = threadIdx.x >> 5, ln = threadIdx.x & 31;
    __syncthreads();
    if (ln == 0) sm[w] = v;
    __syncthreads();
    float r = sm[0];
    #pragma unroll
    for (int i = 1; i < 8; i++) r += sm[i];
    return r;
}

__device__ __forceinline__ uint32_t f2tf32(float f) {
    uint32_t u;
    asm("cvt.rna.tf32.f32 %0, %1;" : "=r"(u) : "f"(f));
    return u;
}

#define MMA_TF32(ACC, A0, A1, A2, A3, B0, B1)                                  \
    asm volatile(                                                              \
        "mma.sync.aligned.m16n8k8.row.col.f32.tf32.tf32.f32 "                  \
        "{%0,%1,%2,%3},{%4,%5,%6,%7},{%8,%9},{%0,%1,%2,%3};"                   \
        : "+f"((ACC)[0]), "+f"((ACC)[1]), "+f"((ACC)[2]), "+f"((ACC)[3])       \
        : "r"(A0), "r"(A1), "r"(A2), "r"(A3), "r"(B0), "r"(B1))

#define CP_ASYNC16(dst, src)                                                   \
    asm volatile("cp.async.ca.shared.global [%0], [%1], 16;" ::                \
                 "r"(dst), "l"(src))
#define CP_COMMIT() asm volatile("cp.async.commit_group;")
#define CP_WAIT2()  asm volatile("cp.async.wait_group 2;")

__device__ __forceinline__ float pe_val(int pos, int d) {
    float div = expf((float)(d & ~1) * (-9.210340371976184f / 1024.0f));
    float ang = (float)pos * div;
    return (d & 1) ? cosf(ang) : sinf(ang);
}

// ---------------- embedding / encoder PE ------------------------------------
__global__ void embed_kernel(const int* __restrict__ tgt,
                             const float* __restrict__ emb,
                             float* __restrict__ x) {
    int row = blockIdx.x;
    int t = row % TGTL;
    int tok = tgt[row];
    const float* er = emb + (size_t)tok * DMODEL;
    float* xr = x + (size_t)row * DMODEL;
    for (int d = threadIdx.x; d < DMODEL; d += blockDim.x)
        xr[d] = er[d] + pe_val(t, d);
}

__global__ void encpe_kernel(const float* __restrict__ src,
                             float* __restrict__ enc) {
    int row = blockIdx.x;
    int s = row % SRCL;
    const float* sr = src + (size_t)row * DMODEL;
    float* er = enc + (size_t)row * DMODEL;
    for (int d = threadIdx.x; d < DMODEL; d += blockDim.x)
        er[d] = sr[d] + pe_val(s, d);
}

// ---------------- TF32 GEMM: cp.async 4-stage pipeline, z-batched ------------
// C[M,N] = A[M,K]@W[K,N] + bias, optional relu. Per-z A/W/bias/C/M.
#define BMt 128
#define BNt 128
#define BKt 16
#define NSTG 4
// smem (floats): As stage stride 128*20=2560, Bs base 4*2560=10240, stage 16*136=2176
#define AS_STRIDE 2560
#define BS_BASE   10240
#define BS_STRIDE 2176
#define GEMM_SMEM ((BS_BASE + NSTG*BS_STRIDE) * 4)   // 75776 bytes

struct GArg3 {
    const float* A[3];
    const float* W[3];
    const float* Bi[3];
    float* C[3];
    int M[3];
};

__global__ void __launch_bounds__(256, 2)
gemm_tf32(GArg3 a3, int N, int K, int relu) {
    int z = blockIdx.z;
    const float* __restrict__ A = a3.A[z];
    const float* __restrict__ W = a3.W[z];
    const float* __restrict__ bias = a3.Bi[z];
    float* __restrict__ C = a3.C[z];
    int M = a3.M[z];

    int m0 = blockIdx.y * BMt, n0 = blockIdx.x * BNt;
    if (m0 >= M) return;

    extern __shared__ float smf[];
    uint32_t smem_u32 = (uint32_t)__cvta_generic_to_shared(smf);

    int tid = threadIdx.x;
    int warp = tid >> 5, lane = tid & 31;
    int g = lane >> 2, c = lane & 3;
    int wm = (warp & 1) * 64, wn = (warp >> 1) * 32;

    // A staging: thread -> row tid>>1, chunks (tid&1)*2, +1 (8 consecutive k)
    int arow = tid >> 1, acl = (tid & 1) * 2;
    const float* Asrc = A + (size_t)(m0 + arow) * K + acl * 4;
    uint32_t Adst = smem_u32 + (arow * 20 + acl * 4) * 4;
    // B staging: thread -> row tid>>4, chunks (tid&15)*2, +1
    int brow = tid >> 4, bcl = (tid & 15) * 2;
    const float* Bsrc = W + (size_t)brow * N + n0 + bcl * 4;
    uint32_t Bdst = smem_u32 + (BS_BASE + brow * 136 + bcl * 4) * 4;

#define ISSUE_STAGE(S, K0)                                                     \
    do {                                                                       \
        uint32_t ad = Adst + (S) * (AS_STRIDE * 4);                            \
        const float* as = Asrc + (K0);                                         \
        CP_ASYNC16(ad, as);                                                    \
        CP_ASYNC16(ad + 16, as + 4);                                           \
        uint32_t bd = Bdst + (S) * (BS_STRIDE * 4);                            \
        const float* bs = Bsrc + (size_t)(K0) * N;                             \
        CP_ASYNC16(bd, bs);                                                    \
        CP_ASYNC16(bd + 16, bs + 4);                                           \
    } while (0)

    float acc[4][4][4] = {};

    int T = K / BKt;
    ISSUE_STAGE(0, 0); CP_COMMIT();
    ISSUE_STAGE(1, BKt); CP_COMMIT();
    ISSUE_STAGE(2, 2 * BKt); CP_COMMIT();

    for (int t = 0; t < T; t++) {
        CP_WAIT2();
        __syncthreads();
        if (t + 3 < T) ISSUE_STAGE((t + 3) & 3, (t + 3) * BKt);
        CP_COMMIT();

        const float* As = smf + (t & 3) * AS_STRIDE;
        const float* Bs = smf + BS_BASE + (t & 3) * BS_STRIDE;
        #pragma unroll
        for (int ks = 0; ks < 2; ks++) {
            int kb = ks * 8;
            uint32_t af[4][4], bf[4][2];
            #pragma unroll
            for (int im = 0; im < 4; im++) {
                int m = wm + im * 16 + g;
                af[im][0] = f2tf32(As[m * 20 + kb + c]);
                af[im][1] = f2tf32(As[(m + 8) * 20 + kb + c]);
                af[im][2] = f2tf32(As[m * 20 + kb + c + 4]);
                af[im][3] = f2tf32(As[(m + 8) * 20 + kb + c + 4]);
            }
            #pragma unroll
            for (int jn = 0; jn < 4; jn++) {
                int n = wn + jn * 8 + g;
                bf[jn][0] = f2tf32(Bs[(kb + c) * 136 + n]);
                bf[jn][1] = f2tf32(Bs[(kb + c + 4) * 136 + n]);
            }
            #pragma unroll
            for (int im = 0; im < 4; im++)
                #pragma unroll
                for (int jn = 0; jn < 4; jn++)
                    MMA_TF32(acc[im][jn], af[im][0], af[im][1], af[im][2],
                             af[im][3], bf[jn][0], bf[jn][1]);
        }
    }
#undef ISSUE_STAGE

    #pragma unroll
    for (int jn = 0; jn < 4; jn++) {
        int col = n0 + wn + jn * 8 + 2 * c;
        float b0v = __ldg(bias + col), b1v = __ldg(bias + col + 1);
        #pragma unroll
        for (int im = 0; im < 4; im++) {
            int row0 = m0 + wm + im * 16 + g;
            float v0 = acc[im][jn][0] + b0v;
            float v1 = acc[im][jn][1] + b1v;
            float v2 = acc[im][jn][2] + b0v;
            float v3 = acc[im][jn][3] + b1v;
            if (relu) {
                v0 = fmaxf(v0, 0.f); v1 = fmaxf(v1, 0.f);
                v2 = fmaxf(v2, 0.f); v3 = fmaxf(v3, 0.f);
            }
            *(float2*)(C + (size_t)row0 * N + col)       = make_float2(v0, v1);
            *(float2*)(C + (size_t)(row0 + 8) * N + col) = make_float2(v2, v3);
        }
    }
}

// ---------------- fused flash attention --------------------------------------
// One block = one (b, h, 64-row q-tile). 128 threads, 4 warps x 16 q-rows.
// Streams K/V in 64-key tiles; online softmax; P reuses K smem buffer.
// NOTE: no causal early-exit — PAD rows need uniform softmax over ALL keys.
#define FLASH_SMEM ((64*68*2 + 64*72) * 4)   // Qs + KPs + Vs = 53248 bytes

__global__ void __launch_bounds__(128)
flash_attn(const float* __restrict__ Q, const float* __restrict__ Kg,
           const float* __restrict__ Vg, float* __restrict__ O,
           int Sk, int causal, const int* __restrict__ tgt) {
    extern __shared__ uint32_t sm_u[];
    uint32_t (*Qs)[68]  = (uint32_t(*)[68])sm_u;
    uint32_t (*KPs)[68] = (uint32_t(*)[68])(sm_u + 64 * 68);
    uint32_t (*Vs)[72]  = (uint32_t(*)[72])(sm_u + 2 * 64 * 68);

    int qt = blockIdx.x, h = blockIdx.y, b = blockIdx.z;
    int tid = threadIdx.x, warp = tid >> 5, lane = tid & 31;
    int g = lane >> 2, c = lane & 3;
    int row = tid >> 1, kg = (tid & 1) * 32;
    int mw = warp * 16;

    // load Q tile [64][64] -> Qs[m][k]
    const float* qp = Q + (size_t)(b * TGTL + qt * 64 + row) * DMODEL + h * 64 + kg;
    #pragma unroll
    for (int u = 0; u < 8; u++) {
        float4 qv = *(const float4*)(qp + u * 4);
        int cc = kg + u * 4;
        Qs[row][cc + 0] = f2tf32(qv.x); Qs[row][cc + 1] = f2tf32(qv.y);
        Qs[row][cc + 2] = f2tf32(qv.z); Qs[row][cc + 3] = f2tf32(qv.w);
    }

    int gi0 = qt * 64 + mw + g, gi1 = gi0 + 8;
    int ok0 = 1, ok1 = 1;
    if (causal) {
        ok0 = (tgt[b * TGTL + gi0] != 0);
        ok1 = (tgt[b * TGTL + gi1] != 0);
    }

    float m0r = -1e30f, m1r = -1e30f, l0 = 0.f, l1 = 0.f;
    float o[8][4] = {};

    int nkt = Sk >> 6;
    for (int kt = 0; kt < nkt; kt++) {
        __syncthreads();   // prior PV reads of KPs/Vs done before overwrite
        const float* kp = Kg + (size_t)(b * Sk + kt * 64 + row) * DMODEL + h * 64 + kg;
        const float* vp = Vg + (size_t)(b * Sk + kt * 64 + row) * DMODEL + h * 64 + kg;
        #pragma unroll
        for (int u = 0; u < 8; u++) {
            float4 kv = *(const float4*)(kp + u * 4);
            int cc = kg + u * 4;
            KPs[row][cc + 0] = f2tf32(kv.x); KPs[row][cc + 1] = f2tf32(kv.y);
            KPs[row][cc + 2] = f2tf32(kv.z); KPs[row][cc + 3] = f2tf32(kv.w);
            float4 vv = *(const float4*)(vp + u * 4);
            Vs[row][cc + 0] = f2tf32(vv.x); Vs[row][cc + 1] = f2tf32(vv.y);
            Vs[row][cc + 2] = f2tf32(vv.z); Vs[row][cc + 3] = f2tf32(vv.w);
        }
        __syncthreads();

        // ---- scores S = Q K^T ----
        float s[8][4] = {};
        #pragma unroll
        for (int kb = 0; kb < 64; kb += 8) {
            uint32_t a0 = Qs[mw + g][kb + c];
            uint32_t a1 = Qs[mw + g + 8][kb + c];
            uint32_t a2 = Qs[mw + g][kb + c + 4];
            uint32_t a3 = Qs[mw + g + 8][kb + c + 4];
            #pragma unroll
            for (int nb = 0; nb < 8; nb++) {
                uint32_t b0 = KPs[nb * 8 + g][kb + c];
                uint32_t b1 = KPs[nb * 8 + g][kb + c + 4];
                MMA_TF32(s[nb], a0, a1, a2, a3, b0, b1);
            }
        }
        // scale + mask
        #pragma unroll
        for (int nb = 0; nb < 8; nb++) {
            int gj = kt * 64 + nb * 8 + 2 * c;
            s[nb][0] *= 0.125f; s[nb][1] *= 0.125f;
            s[nb][2] *= 0.125f; s[nb][3] *= 0.125f;
            if (causal) {
                if (gj > gi0 || !ok0)     s[nb][0] = -1e9f;
                if (gj + 1 > gi0 || !ok0) s[nb][1] = -1e9f;
                if (gj > gi1 || !ok1)     s[nb][2] = -1e9f;
                if (gj + 1 > gi1 || !ok1) s[nb][3] = -1e9f;
            }
        }
        // ---- online softmax ----
        float t0 = -1e30f, t1 = -1e30f;
        #pragma unroll
        for (int nb = 0; nb < 8; nb++) {
            t0 = fmaxf(t0, fmaxf(s[nb][0], s[nb][1]));
            t1 = fmaxf(t1, fmaxf(s[nb][2], s[nb][3]));
        }
        t0 = fmaxf(t0, __shfl_xor_sync(0xffffffffu, t0, 1));
        t0 = fmaxf(t0, __shfl_xor_sync(0xffffffffu, t0, 2));
        t1 = fmaxf(t1, __shfl_xor_sync(0xffffffffu, t1, 1));
        t1 = fmaxf(t1, __shfl_xor_sync(0xffffffffu, t1, 2));
        float nm0 = fmaxf(m0r, t0), nm1 = fmaxf(m1r, t1);
        float f0 = expf(m0r - nm0), f1 = expf(m1r - nm1);
        float ts0 = 0.f, ts1 = 0.f;
        #pragma unroll
        for (int nb = 0; nb < 8; nb++) {
            s[nb][0] = expf(s[nb][0] - nm0);
            s[nb][1] = expf(s[nb][1] - nm0);
            s[nb][2] = expf(s[nb][2] - nm1);
            s[nb][3] = expf(s[nb][3] - nm1);
            ts0 += s[nb][0] + s[nb][1];
            ts1 += s[nb][2] + s[nb][3];
        }
        ts0 += __shfl_xor_sync(0xffffffffu, ts0, 1);
        ts0 += __shfl_xor_sync(0xffffffffu, ts0, 2);
        ts1 += __shfl_xor_sync(0xffffffffu, ts1, 1);
        ts1 += __shfl_xor_sync(0xffffffffu, ts1, 2);
        l0 = l0 * f0 + ts0;
        l1 = l1 * f1 + ts1;
        m0r = nm0; m1r = nm1;
        #pragma unroll
        for (int nb = 0; nb < 8; nb++) {
            o[nb][0] *= f0; o[nb][1] *= f0;
            o[nb][2] *= f1; o[nb][3] *= f1;
        }
        // ---- write P into KPs (reuse) ----
        __syncthreads();   // all warps done reading K from KPs
        #pragma unroll
        for (int nb = 0; nb < 8; nb++) {
            int cc = nb * 8 + 2 * c;
            KPs[mw + g][cc]     = f2tf32(s[nb][0]);
            KPs[mw + g][cc + 1] = f2tf32(s[nb][1]);
            KPs[mw + g + 8][cc]     = f2tf32(s[nb][2]);
            KPs[mw + g + 8][cc + 1] = f2tf32(s[nb][3]);
        }
        __syncthreads();
        // ---- O += P @ V ----
        #pragma unroll
        for (int kb = 0; kb < 64; kb += 8) {
            uint32_t a0 = KPs[mw + g][kb + c];
            uint32_t a1 = KPs[mw + g + 8][kb + c];
            uint32_t a2 = KPs[mw + g][kb + c + 4];
            uint32_t a3 = KPs[mw + g + 8][kb + c + 4];
            #pragma unroll
            for (int nb = 0; nb < 8; nb++) {
                uint32_t b0 = Vs[kb + c][nb * 8 + g];
                uint32_t b1 = Vs[kb + c + 4][nb * 8 + g];
                MMA_TF32(o[nb], a0, a1, a2, a3, b0, b1);
            }
        }
    }

    float inv0 = 1.0f / l0, inv1 = 1.0f / l1;
    #pragma unroll
    for (int nb = 0; nb < 8; nb++) {
        int col = h * 64 + nb * 8 + 2 * c;
        size_t r0 = (size_t)(b * TGTL + qt * 64 + mw + g);
        *(float2*)(O + r0 * DMODEL + col) =
            make_float2(o[nb][0] * inv0, o[nb][1] * inv0);
        *(float2*)(O + (r0 + 8) * DMODEL + col) =
            make_float2(o[nb][2] * inv1, o[nb][3] * inv1);
    }
}

// ---------------- fused residual + LayerNorm (x = LN(x + a)) ----------------
__global__ void ln_res(float* __restrict__ x, const float* __restrict__ a,
                       const float* __restrict__ g, const float* __restrict__ bb) {
    int row = blockIdx.x, tid = threadIdx.x;
    float* xr = x + (size_t)row * DMODEL;
    const float* ar = a + (size_t)row * DMODEL;
    float v[4];
    float s = 0.f;
    #pragma unroll
    for (int u = 0; u < 4; u++) {
        int i = tid + u * 256;
        v[u] = xr[i] + ar[i];
        s += v[u];
    }
    s = blkReduceSum(s);
    float mu = s * (1.0f / DMODEL);
    float q = 0.f;
    #pragma unroll
    for (int u = 0; u < 4; u++) { float d = v[u] - mu; q += d * d; }
    q = blkReduceSum(q);
    float rs = rsqrtf(q * (1.0f / DMODEL) + 1e-5f);
    #pragma unroll
    for (int u = 0; u < 4; u++) {
        int i = tid + u * 256;
        xr[i] = (v[u] - mu) * rs * g[i] + bb[i];
    }
}

// ---------------- host orchestration ----------------------------------------
static inline GArg3 g1(const float* A, const float* W, const float* B, float* C,
                       int M) {
    GArg3 t;
    for (int i = 0; i < 3; i++) {
        t.A[i] = A; t.W[i] = W; t.Bi[i] = B; t.C[i] = C; t.M[i] = M;
    }
    return t;
}

extern "C" void kernel_launch(void* const* d_in, const int* in_sizes, int n_in,
                              void* d_out, int out_size) {
    (void)n_in; (void)out_size;
    int dict = (in_sizes[3] == 32768000);
    int base, iFCW, iFCB, iN1G, iN1B, iN2G, iN2B, iN3G, iN3B;
    if (dict) {
        iFCW = 3; iFCB = 4; base = 5;
        iN1G = base + 20; iN2G = base + 21; iN3G = base + 22;
        iN1B = base + 23; iN2B = base + 24; iN3B = base + 25;
    } else {
        base = 3; iFCW = 29; iFCB = 30;
        iN1G = base + 20; iN1B = base + 21; iN2G = base + 22;
        iN2B = base + 23; iN3G = base + 24; iN3B = base + 25;
    }
    const float* src  = (const float*)d_in[0];
    const int*   tgt  = (const int*)d_in[1];
    const float* emb  = (const float*)d_in[2];
    const float* fcw  = (const float*)d_in[iFCW];
    const float* fcb  = (const float*)d_in[iFCB];
    const float* AP[16];
    for (int i = 0; i < 16; i++) AP[i] = (const float*)d_in[base + i];
    const float* w1 = (const float*)d_in[base + 16];
    const float* b1 = (const float*)d_in[base + 17];
    const float* w2 = (const float*)d_in[base + 18];
    const float* b2 = (const float*)d_in[base + 19];
    const float* n1g = (const float*)d_in[iN1G];
    const float* n1b = (const float*)d_in[iN1B];
    const float* n2g = (const float*)d_in[iN2G];
    const float* n2b = (const float*)d_in[iN2B];
    const float* n3g = (const float*)d_in[iN3G];
    const float* n3b = (const float*)d_in[iN3B];

    float *x, *enc, *q, *k, *v, *attn, *proj, *ffn;
    cudaGetSymbolAddress((void**)&x,    g_x);
    cudaGetSymbolAddress((void**)&enc,  g_enc);
    cudaGetSymbolAddress((void**)&q,    g_q);
    cudaGetSymbolAddress((void**)&k,    g_k);
    cudaGetSymbolAddress((void**)&v,    g_v);
    cudaGetSymbolAddress((void**)&attn, g_attn);
    cudaGetSymbolAddress((void**)&proj, g_proj);
    cudaGetSymbolAddress((void**)&ffn,  g_ffn);

    cudaFuncSetAttribute(gemm_tf32, cudaFuncAttributeMaxDynamicSharedMemorySize,
                         GEMM_SMEM);
    cudaFuncSetAttribute(flash_attn, cudaFuncAttributeMaxDynamicSharedMemorySize,
                         FLASH_SMEM);

    encpe_kernel<<<NE, 256>>>(src, enc);
    embed_kernel<<<NQ, 256>>>(tgt, emb, x);

    dim3 gDD(DMODEL / BNt, NQ / BMt, 1);   // 8 x 16
    dim3 gDD3(DMODEL / BNt, NQ / BMt, 3);  // batched QKV / cross QKV
    dim3 gFF(DFF / BNt, NQ / BMt, 1);      // 32 x 16

    for (int l = 0; l < NLAYER; l++) {
        size_t ow = (size_t)l * DMODEL * DMODEL, ob = (size_t)l * DMODEL;
        size_t ow1 = (size_t)l * DMODEL * DFF, ob1 = (size_t)l * DFF;

        // ---- self attention: batched QKV ----
        GArg3 qkv;
        qkv.A[0] = x; qkv.W[0] = AP[0] + ow; qkv.Bi[0] = AP[1] + ob; qkv.C[0] = q; qkv.M[0] = NQ;
        qkv.A[1] = x; qkv.W[1] = AP[2] + ow; qkv.Bi[1] = AP[3] + ob; qkv.C[1] = k; qkv.M[1] = NQ;
        qkv.A[2] = x; qkv.W[2] = AP[4] + ow; qkv.Bi[2] = AP[5] + ob; qkv.C[2] = v; qkv.M[2] = NQ;
        gemm_tf32<<<gDD3, 256, GEMM_SMEM>>>(qkv, DMODEL, DMODEL, 0);
        flash_attn<<<dim3(8, NHEAD, Bsz), 128, FLASH_SMEM>>>(q, k, v, attn,
                                                             TGTL, 1, tgt);
        gemm_tf32<<<gDD, 256, GEMM_SMEM>>>(
            g1(attn, AP[6] + ow, AP[7] + ob, proj, NQ), DMODEL, DMODEL, 0);
        ln_res<<<NQ, 256>>>(x, proj, n1g + ob, n1b + ob);

        // ---- cross attention: fused Q (on x) + K,V (on enc) ----
        GArg3 ckv;
        ckv.A[0] = x;   ckv.W[0] = AP[8]  + ow; ckv.Bi[0] = AP[9]  + ob; ckv.C[0] = q; ckv.M[0] = NQ;
        ckv.A[1] = enc; ckv.W[1] = AP[10] + ow; ckv.Bi[1] = AP[11] + ob; ckv.C[1] = k; ckv.M[1] = NE;
        ckv.A[2] = enc; ckv.W[2] = AP[12] + ow; ckv.Bi[2] = AP[13] + ob; ckv.C[2] = v; ckv.M[2] = NE;
        gemm_tf32<<<gDD3, 256, GEMM_SMEM>>>(ckv, DMODEL, DMODEL, 0);
        flash_attn<<<dim3(8, NHEAD, Bsz), 128, FLASH_SMEM>>>(q, k, v, attn,
                                                             SRCL, 0, tgt);
        gemm_tf32<<<gDD, 256, GEMM_SMEM>>>(
            g1(attn, AP[14] + ow, AP[15] + ob, proj, NQ), DMODEL, DMODEL, 0);
        ln_res<<<NQ, 256>>>(x, proj, n2g + ob, n2b + ob);

        // ---- feed forward ----
        gemm_tf32<<<gFF, 256, GEMM_SMEM>>>(
            g1(x, w1 + ow1, b1 + ob1, ffn, NQ), DFF, DMODEL, 1);
        gemm_tf32<<<gDD, 256, GEMM_SMEM>>>(
            g1(ffn, w2 + ow1, b2 + ob, proj, NQ), DMODEL, DFF, 0);
        ln_res<<<NQ, 256>>>(x, proj, n3g + ob, n3b + ob);
    }

    // ---- final projection to vocab ----
    gemm_tf32<<<dim3(VOC / BNt, NQ / BMt, 1), 256, GEMM_SMEM>>>(
        g1(x, fcw, fcb, (float*)d_out, NQ), VOC, DMODEL, 0);
}

// round 7
// speedup vs baseline: 3.0113x; 1.0124x over previous
#include <cuda_runtime.h>
#include <math.h>
#include <stdint.h>

#define Bsz 4
#define SRCL 256
#define TGTL 512
#define DMODEL 1024
#define NHEAD 16
#define DKH 64
#define NLAYER 8
#define DFF 4096
#define VOC 32000
#define NQ (Bsz*TGTL)
#define NE (Bsz*SRCL)

// ---------------- scratch (device globals; no allocations allowed) ----------
__device__ float g_x[NQ*DMODEL];
__device__ float g_enc[NE*DMODEL];
__device__ float g_q[NQ*DMODEL];
__device__ float g_k[NQ*DMODEL];
__device__ float g_v[NQ*DMODEL];
__device__ float g_attn[NQ*DMODEL];
__device__ float g_proj[NQ*DMODEL];
__device__ float g_ffn[NQ*DFF];

// ---------------- helpers ---------------------------------------------------
__device__ __forceinline__ float blkReduceSum(float v) {
    #pragma unroll
    for (int o = 16; o > 0; o >>= 1) v += __shfl_xor_sync(0xffffffffu, v, o);
    __shared__ float sm[8];
    int w = threadIdx.x >> 5, ln = threadIdx.x & 31;
    __syncthreads();
    if (ln == 0) sm[w] = v;
    __syncthreads();
    float r = sm[0];
    #pragma unroll
    for (int i = 1; i < 8; i++) r += sm[i];
    return r;
}

__device__ __forceinline__ uint32_t f2tf32(float f) {
    uint32_t u;
    asm("cvt.rna.tf32.f32 %0, %1;" : "=r"(u) : "f"(f));
    return u;
}

#define MMA_TF32(ACC, A0, A1, A2, A3, B0, B1)                                  \
    asm volatile(                                                              \
        "mma.sync.aligned.m16n8k8.row.col.f32.tf32.tf32.f32 "                  \
        "{%0,%1,%2,%3},{%4,%5,%6,%7},{%8,%9},{%0,%1,%2,%3};"                   \
        : "+f"((ACC)[0]), "+f"((ACC)[1]), "+f"((ACC)[2]), "+f"((ACC)[3])       \
        : "r"(A0), "r"(A1), "r"(A2), "r"(A3), "r"(B0), "r"(B1))

#define CP_ASYNC16(dst, src)                                                   \
    asm volatile("cp.async.ca.shared.global [%0], [%1], 16;" ::                \
                 "r"(dst), "l"(src))
#define CP_COMMIT() asm volatile("cp.async.commit_group;")
#define CP_WAIT2()  asm volatile("cp.async.wait_group 2;")

__device__ __forceinline__ float pe_val(int pos, int d) {
    float div = expf((float)(d & ~1) * (-9.210340371976184f / 1024.0f));
    float ang = (float)pos * div;
    return (d & 1) ? cosf(ang) : sinf(ang);
}

// ---------------- embedding / encoder PE ------------------------------------
__global__ void embed_kernel(const int* __restrict__ tgt,
                             const float* __restrict__ emb,
                             float* __restrict__ x) {
    int row = blockIdx.x;
    int t = row % TGTL;
    int tok = tgt[row];
    const float* er = emb + (size_t)tok * DMODEL;
    float* xr = x + (size_t)row * DMODEL;
    for (int d = threadIdx.x; d < DMODEL; d += blockDim.x)
        xr[d] = er[d] + pe_val(t, d);
}

__global__ void encpe_kernel(const float* __restrict__ src,
                             float* __restrict__ enc) {
    int row = blockIdx.x;
    int s = row % SRCL;
    const float* sr = src + (size_t)row * DMODEL;
    float* er = enc + (size_t)row * DMODEL;
    for (int d = threadIdx.x; d < DMODEL; d += blockDim.x)
        er[d] = sr[d] + pe_val(s, d);
}

// ---------------- TF32 GEMM: cp.async 4-stage pipeline, z-batched ------------
#define BMt 128
#define BNt 128
#define BKt 16
#define NSTG 4
#define AS_STRIDE 2560
#define BS_BASE   10240
#define BS_STRIDE 2176
#define GEMM_SMEM ((BS_BASE + NSTG*BS_STRIDE) * 4)

struct GArg3 {
    const float* A[3];
    const float* W[3];
    const float* Bi[3];
    float* C[3];
    int M[3];
};

__global__ void __launch_bounds__(256, 2)
gemm_tf32(GArg3 a3, int N, int K, int relu) {
    int z = blockIdx.z;
    const float* __restrict__ A = a3.A[z];
    const float* __restrict__ W = a3.W[z];
    const float* __restrict__ bias = a3.Bi[z];
    float* __restrict__ C = a3.C[z];
    int M = a3.M[z];

    int m0 = blockIdx.y * BMt, n0 = blockIdx.x * BNt;
    if (m0 >= M) return;

    extern __shared__ float smf[];
    uint32_t smem_u32 = (uint32_t)__cvta_generic_to_shared(smf);

    int tid = threadIdx.x;
    int warp = tid >> 5, lane = tid & 31;
    int g = lane >> 2, c = lane & 3;
    int wm = (warp & 1) * 64, wn = (warp >> 1) * 32;

    int arow = tid >> 1, acl = (tid & 1) * 2;
    const float* Asrc = A + (size_t)(m0 + arow) * K + acl * 4;
    uint32_t Adst = smem_u32 + (arow * 20 + acl * 4) * 4;
    int brow = tid >> 4, bcl = (tid & 15) * 2;
    const float* Bsrc = W + (size_t)brow * N + n0 + bcl * 4;
    uint32_t Bdst = smem_u32 + (BS_BASE + brow * 136 + bcl * 4) * 4;

#define ISSUE_STAGE(S, K0)                                                     \
    do {                                                                       \
        uint32_t ad = Adst + (S) * (AS_STRIDE * 4);                            \
        const float* as = Asrc + (K0);                                         \
        CP_ASYNC16(ad, as);                                                    \
        CP_ASYNC16(ad + 16, as + 4);                                           \
        uint32_t bd = Bdst + (S) * (BS_STRIDE * 4);                            \
        const float* bs = Bsrc + (size_t)(K0) * N;                             \
        CP_ASYNC16(bd, bs);                                                    \
        CP_ASYNC16(bd + 16, bs + 4);                                           \
    } while (0)

    float acc[4][4][4] = {};

    int T = K / BKt;
    ISSUE_STAGE(0, 0); CP_COMMIT();
    ISSUE_STAGE(1, BKt); CP_COMMIT();
    ISSUE_STAGE(2, 2 * BKt); CP_COMMIT();

    for (int t = 0; t < T; t++) {
        CP_WAIT2();
        __syncthreads();
        if (t + 3 < T) ISSUE_STAGE((t + 3) & 3, (t + 3) * BKt);
        CP_COMMIT();

        const float* As = smf + (t & 3) * AS_STRIDE;
        const float* Bs = smf + BS_BASE + (t & 3) * BS_STRIDE;
        #pragma unroll
        for (int ks = 0; ks < 2; ks++) {
            int kb = ks * 8;
            uint32_t af[4][4], bf[4][2];
            #pragma unroll
            for (int im = 0; im < 4; im++) {
                int m = wm + im * 16 + g;
                af[im][0] = f2tf32(As[m * 20 + kb + c]);
                af[im][1] = f2tf32(As[(m + 8) * 20 + kb + c]);
                af[im][2] = f2tf32(As[m * 20 + kb + c + 4]);
                af[im][3] = f2tf32(As[(m + 8) * 20 + kb + c + 4]);
            }
            #pragma unroll
            for (int jn = 0; jn < 4; jn++) {
                int n = wn + jn * 8 + g;
                bf[jn][0] = f2tf32(Bs[(kb + c) * 136 + n]);
                bf[jn][1] = f2tf32(Bs[(kb + c + 4) * 136 + n]);
            }
            #pragma unroll
            for (int im = 0; im < 4; im++)
                #pragma unroll
                for (int jn = 0; jn < 4; jn++)
                    MMA_TF32(acc[im][jn], af[im][0], af[im][1], af[im][2],
                             af[im][3], bf[jn][0], bf[jn][1]);
        }
    }
#undef ISSUE_STAGE

    #pragma unroll
    for (int jn = 0; jn < 4; jn++) {
        int col = n0 + wn + jn * 8 + 2 * c;
        float b0v = __ldg(bias + col), b1v = __ldg(bias + col + 1);
        #pragma unroll
        for (int im = 0; im < 4; im++) {
            int row0 = m0 + wm + im * 16 + g;
            float v0 = acc[im][jn][0] + b0v;
            float v1 = acc[im][jn][1] + b1v;
            float v2 = acc[im][jn][2] + b0v;
            float v3 = acc[im][jn][3] + b1v;
            if (relu) {
                v0 = fmaxf(v0, 0.f); v1 = fmaxf(v1, 0.f);
                v2 = fmaxf(v2, 0.f); v3 = fmaxf(v3, 0.f);
            }
            *(float2*)(C + (size_t)row0 * N + col)       = make_float2(v0, v1);
            *(float2*)(C + (size_t)(row0 + 8) * N + col) = make_float2(v2, v3);
        }
    }
}

// ---------------- fused flash attention --------------------------------------
// One block = one (b, h, 64-row q-tile). 128 threads, 4 warps x 16 q-rows.
// Upper-triangle tiles (kt > qt, causal): all scores are -1e9 regardless of
// Q/K, so skip the K load + QK MMA but STILL run exp/PV (PAD rows need the
// uniform-softmax contribution: p=1 there, 0 for valid rows).
#define FLASH_SMEM ((64*68*2 + 64*72) * 4)

__global__ void __launch_bounds__(128)
flash_attn(const float* __restrict__ Q, const float* __restrict__ Kg,
           const float* __restrict__ Vg, float* __restrict__ O,
           int Sk, int causal, const int* __restrict__ tgt) {
    extern __shared__ uint32_t sm_u[];
    uint32_t (*Qs)[68]  = (uint32_t(*)[68])sm_u;
    uint32_t (*KPs)[68] = (uint32_t(*)[68])(sm_u + 64 * 68);
    uint32_t (*Vs)[72]  = (uint32_t(*)[72])(sm_u + 2 * 64 * 68);

    int qt = blockIdx.x, h = blockIdx.y, b = blockIdx.z;
    int tid = threadIdx.x, warp = tid >> 5, lane = tid & 31;
    int g = lane >> 2, c = lane & 3;
    int row = tid >> 1, kg = (tid & 1) * 32;
    int mw = warp * 16;

    const float* qp = Q + (size_t)(b * TGTL + qt * 64 + row) * DMODEL + h * 64 + kg;
    #pragma unroll
    for (int u = 0; u < 8; u++) {
        float4 qv = *(const float4*)(qp + u * 4);
        int cc = kg + u * 4;
        Qs[row][cc + 0] = f2tf32(qv.x); Qs[row][cc + 1] = f2tf32(qv.y);
        Qs[row][cc + 2] = f2tf32(qv.z); Qs[row][cc + 3] = f2tf32(qv.w);
    }

    int gi0 = qt * 64 + mw + g, gi1 = gi0 + 8;
    int ok0 = 1, ok1 = 1;
    if (causal) {
        ok0 = (tgt[b * TGTL + gi0] != 0);
        ok1 = (tgt[b * TGTL + gi1] != 0);
    }

    float m0r = -1e30f, m1r = -1e30f, l0 = 0.f, l1 = 0.f;
    float o[8][4] = {};

    int nkt = Sk >> 6;
    for (int kt = 0; kt < nkt; kt++) {
        bool skipk = (causal != 0) && (kt > qt);   // uniform across block
        __syncthreads();
        const float* vp = Vg + (size_t)(b * Sk + kt * 64 + row) * DMODEL + h * 64 + kg;
        if (!skipk) {
            const float* kp = Kg + (size_t)(b * Sk + kt * 64 + row) * DMODEL + h * 64 + kg;
            #pragma unroll
            for (int u = 0; u < 8; u++) {
                float4 kv = *(const float4*)(kp + u * 4);
                int cc = kg + u * 4;
                KPs[row][cc + 0] = f2tf32(kv.x); KPs[row][cc + 1] = f2tf32(kv.y);
                KPs[row][cc + 2] = f2tf32(kv.z); KPs[row][cc + 3] = f2tf32(kv.w);
            }
        }
        #pragma unroll
        for (int u = 0; u < 8; u++) {
            float4 vv = *(const float4*)(vp + u * 4);
            int cc = kg + u * 4;
            Vs[row][cc + 0] = f2tf32(vv.x); Vs[row][cc + 1] = f2tf32(vv.y);
            Vs[row][cc + 2] = f2tf32(vv.z); Vs[row][cc + 3] = f2tf32(vv.w);
        }
        __syncthreads();

        // ---- scores S = Q K^T (or all -1e9 for skipped tiles) ----
        float s[8][4];
        if (!skipk) {
            #pragma unroll
            for (int nb = 0; nb < 8; nb++)
                s[nb][0] = s[nb][1] = s[nb][2] = s[nb][3] = 0.f;
            #pragma unroll
            for (int kb = 0; kb < 64; kb += 8) {
                uint32_t a0 = Qs[mw + g][kb + c];
                uint32_t a1 = Qs[mw + g + 8][kb + c];
                uint32_t a2 = Qs[mw + g][kb + c + 4];
                uint32_t a3 = Qs[mw + g + 8][kb + c + 4];
                #pragma unroll
                for (int nb = 0; nb < 8; nb++) {
                    uint32_t b0 = KPs[nb * 8 + g][kb + c];
                    uint32_t b1 = KPs[nb * 8 + g][kb + c + 4];
                    MMA_TF32(s[nb], a0, a1, a2, a3, b0, b1);
                }
            }
            #pragma unroll
            for (int nb = 0; nb < 8; nb++) {
                int gj = kt * 64 + nb * 8 + 2 * c;
                s[nb][0] *= 0.125f; s[nb][1] *= 0.125f;
                s[nb][2] *= 0.125f; s[nb][3] *= 0.125f;
                if (causal) {
                    if (gj > gi0 || !ok0)     s[nb][0] = -1e9f;
                    if (gj + 1 > gi0 || !ok0) s[nb][1] = -1e9f;
                    if (gj > gi1 || !ok1)     s[nb][2] = -1e9f;
                    if (gj + 1 > gi1 || !ok1) s[nb][3] = -1e9f;
                }
            }
        } else {
            #pragma unroll
            for (int nb = 0; nb < 8; nb++)
                s[nb][0] = s[nb][1] = s[nb][2] = s[nb][3] = -1e9f;
        }

        // ---- online softmax ----
        float t0 = -1e30f, t1 = -1e30f;
        #pragma unroll
        for (int nb = 0; nb < 8; nb++) {
            t0 = fmaxf(t0, fmaxf(s[nb][0], s[nb][1]));
            t1 = fmaxf(t1, fmaxf(s[nb][2], s[nb][3]));
        }
        t0 = fmaxf(t0, __shfl_xor_sync(0xffffffffu, t0, 1));
        t0 = fmaxf(t0, __shfl_xor_sync(0xffffffffu, t0, 2));
        t1 = fmaxf(t1, __shfl_xor_sync(0xffffffffu, t1, 1));
        t1 = fmaxf(t1, __shfl_xor_sync(0xffffffffu, t1, 2));
        float nm0 = fmaxf(m0r, t0), nm1 = fmaxf(m1r, t1);
        float f0 = __expf(m0r - nm0), f1 = __expf(m1r - nm1);
        float ts0 = 0.f, ts1 = 0.f;
        #pragma unroll
        for (int nb = 0; nb < 8; nb++) {
            s[nb][0] = __expf(s[nb][0] - nm0);
            s[nb][1] = __expf(s[nb][1] - nm0);
            s[nb][2] = __expf(s[nb][2] - nm1);
            s[nb][3] = __expf(s[nb][3] - nm1);
            ts0 += s[nb][0] + s[nb][1];
            ts1 += s[nb][2] + s[nb][3];
        }
        ts0 += __shfl_xor_sync(0xffffffffu, ts0, 1);
        ts0 += __shfl_xor_sync(0xffffffffu, ts0, 2);
        ts1 += __shfl_xor_sync(0xffffffffu, ts1, 1);
        ts1 += __shfl_xor_sync(0xffffffffu, ts1, 2);
        l0 = l0 * f0 + ts0;
        l1 = l1 * f1 + ts1;
        m0r = nm0; m1r = nm1;
        #pragma unroll
        for (int nb = 0; nb < 8; nb++) {
            o[nb][0] *= f0; o[nb][1] *= f0;
            o[nb][2] *= f1; o[nb][3] *= f1;
        }
        // ---- write P into KPs (reuse) ----
        __syncthreads();
        #pragma unroll
        for (int nb = 0; nb < 8; nb++) {
            int cc = nb * 8 + 2 * c;
            KPs[mw + g][cc]     = f2tf32(s[nb][0]);
            KPs[mw + g][cc + 1] = f2tf32(s[nb][1]);
            KPs[mw + g + 8][cc]     = f2tf32(s[nb][2]);
            KPs[mw + g + 8][cc + 1] = f2tf32(s[nb][3]);
        }
        __syncthreads();
        // ---- O += P @ V ----
        #pragma unroll
        for (int kb = 0; kb < 64; kb += 8) {
            uint32_t a0 = KPs[mw + g][kb + c];
            uint32_t a1 = KPs[mw + g + 8][kb + c];
            uint32_t a2 = KPs[mw + g][kb + c + 4];
            uint32_t a3 = KPs[mw + g + 8][kb + c + 4];
            #pragma unroll
            for (int nb = 0; nb < 8; nb++) {
                uint32_t b0 = Vs[kb + c][nb * 8 + g];
                uint32_t b1 = Vs[kb + c + 4][nb * 8 + g];
                MMA_TF32(o[nb], a0, a1, a2, a3, b0, b1);
            }
        }
    }

    float inv0 = 1.0f / l0, inv1 = 1.0f / l1;
    #pragma unroll
    for (int nb = 0; nb < 8; nb++) {
        int col = h * 64 + nb * 8 + 2 * c;
        size_t r0 = (size_t)(b * TGTL + qt * 64 + mw + g);
        *(float2*)(O + r0 * DMODEL + col) =
            make_float2(o[nb][0] * inv0, o[nb][1] * inv0);
        *(float2*)(O + (r0 + 8) * DMODEL + col) =
            make_float2(o[nb][2] * inv1, o[nb][3] * inv1);
    }
}

// ---------------- fused residual + LayerNorm (x = LN(x + a)) ----------------
__global__ void ln_res(float* __restrict__ x, const float* __restrict__ a,
                       const float* __restrict__ g, const float* __restrict__ bb) {
    int row = blockIdx.x, tid = threadIdx.x;
    float4* xr4 = (float4*)(x + (size_t)row * DMODEL);
    const float4* ar4 = (const float4*)(a + (size_t)row * DMODEL);
    float4 v = xr4[tid];
    float4 av = ar4[tid];
    v.x += av.x; v.y += av.y; v.z += av.z; v.w += av.w;
    float s = v.x + v.y + v.z + v.w;
    s = blkReduceSum(s);
    float mu = s * (1.0f / DMODEL);
    float dx = v.x - mu, dy = v.y - mu, dz = v.z - mu, dw = v.w - mu;
    float q = dx * dx + dy * dy + dz * dz + dw * dw;
    q = blkReduceSum(q);
    float rs = rsqrtf(q * (1.0f / DMODEL) + 1e-5f);
    float4 gv = ((const float4*)g)[tid];
    float4 bv = ((const float4*)bb)[tid];
    float4 o;
    o.x = dx * rs * gv.x + bv.x;
    o.y = dy * rs * gv.y + bv.y;
    o.z = dz * rs * gv.z + bv.z;
    o.w = dw * rs * gv.w + bv.w;
    xr4[tid] = o;
}

// ---------------- host orchestration ----------------------------------------
static inline GArg3 g1(const float* A, const float* W, const float* B, float* C,
                       int M) {
    GArg3 t;
    for (int i = 0; i < 3; i++) {
        t.A[i] = A; t.W[i] = W; t.Bi[i] = B; t.C[i] = C; t.M[i] = M;
    }
    return t;
}

extern "C" void kernel_launch(void* const* d_in, const int* in_sizes, int n_in,
                              void* d_out, int out_size) {
    (void)n_in; (void)out_size;
    int dict = (in_sizes[3] == 32768000);
    int base, iFCW, iFCB, iN1G, iN1B, iN2G, iN2B, iN3G, iN3B;
    if (dict) {
        iFCW = 3; iFCB = 4; base = 5;
        iN1G = base + 20; iN2G = base + 21; iN3G = base + 22;
        iN1B = base + 23; iN2B = base + 24; iN3B = base + 25;
    } else {
        base = 3; iFCW = 29; iFCB = 30;
        iN1G = base + 20; iN1B = base + 21; iN2G = base + 22;
        iN2B = base + 23; iN3G = base + 24; iN3B = base + 25;
    }
    const float* src  = (const float*)d_in[0];
    const int*   tgt  = (const int*)d_in[1];
    const float* emb  = (const float*)d_in[2];
    const float* fcw  = (const float*)d_in[iFCW];
    const float* fcb  = (const float*)d_in[iFCB];
    const float* AP[16];
    for (int i = 0; i < 16; i++) AP[i] = (const float*)d_in[base + i];
    const float* w1 = (const float*)d_in[base + 16];
    const float* b1 = (const float*)d_in[base + 17];
    const float* w2 = (const float*)d_in[base + 18];
    const float* b2 = (const float*)d_in[base + 19];
    const float* n1g = (const float*)d_in[iN1G];
    const float* n1b = (const float*)d_in[iN1B];
    const float* n2g = (const float*)d_in[iN2G];
    const float* n2b = (const float*)d_in[iN2B];
    const float* n3g = (const float*)d_in[iN3G];
    const float* n3b = (const float*)d_in[iN3B];

    float *x, *enc, *q, *k, *v, *attn, *proj, *ffn;
    cudaGetSymbolAddress((void**)&x,    g_x);
    cudaGetSymbolAddress((void**)&enc,  g_enc);
    cudaGetSymbolAddress((void**)&q,    g_q);
    cudaGetSymbolAddress((void**)&k,    g_k);
    cudaGetSymbolAddress((void**)&v,    g_v);
    cudaGetSymbolAddress((void**)&attn, g_attn);
    cudaGetSymbolAddress((void**)&proj, g_proj);
    cudaGetSymbolAddress((void**)&ffn,  g_ffn);

    cudaFuncSetAttribute(gemm_tf32, cudaFuncAttributeMaxDynamicSharedMemorySize,
                         GEMM_SMEM);
    cudaFuncSetAttribute(flash_attn, cudaFuncAttributeMaxDynamicSharedMemorySize,
                         FLASH_SMEM);

    encpe_kernel<<<NE, 256>>>(src, enc);
    embed_kernel<<<NQ, 256>>>(tgt, emb, x);

    dim3 gDD(DMODEL / BNt, NQ / BMt, 1);
    dim3 gDD3(DMODEL / BNt, NQ / BMt, 3);
    dim3 gFF(DFF / BNt, NQ / BMt, 1);

    for (int l = 0; l < NLAYER; l++) {
        size_t ow = (size_t)l * DMODEL * DMODEL, ob = (size_t)l * DMODEL;
        size_t ow1 = (size_t)l * DMODEL * DFF, ob1 = (size_t)l * DFF;

        // ---- self attention: batched QKV ----
        GArg3 qkv;
        qkv.A[0] = x; qkv.W[0] = AP[0] + ow; qkv.Bi[0] = AP[1] + ob; qkv.C[0] = q; qkv.M[0] = NQ;
        qkv.A[1] = x; qkv.W[1] = AP[2] + ow; qkv.Bi[1] = AP[3] + ob; qkv.C[1] = k; qkv.M[1] = NQ;
        qkv.A[2] = x; qkv.W[2] = AP[4] + ow; qkv.Bi[2] = AP[5] + ob; qkv.C[2] = v; qkv.M[2] = NQ;
        gemm_tf32<<<gDD3, 256, GEMM_SMEM>>>(qkv, DMODEL, DMODEL, 0);
        flash_attn<<<dim3(8, NHEAD, Bsz), 128, FLASH_SMEM>>>(q, k, v, attn,
                                                             TGTL, 1, tgt);
        gemm_tf32<<<gDD, 256, GEMM_SMEM>>>(
            g1(attn, AP[6] + ow, AP[7] + ob, proj, NQ), DMODEL, DMODEL, 0);
        ln_res<<<NQ, 256>>>(x, proj, n1g + ob, n1b + ob);

        // ---- cross attention: fused Q (on x) + K,V (on enc) ----
        GArg3 ckv;
        ckv.A[0] = x;   ckv.W[0] = AP[8]  + ow; ckv.Bi[0] = AP[9]  + ob; ckv.C[0] = q; ckv.M[0] = NQ;
        ckv.A[1] = enc; ckv.W[1] = AP[10] + ow; ckv.Bi[1] = AP[11] + ob; ckv.C[1] = k; ckv.M[1] = NE;
        ckv.A[2] = enc; ckv.W[2] = AP[12] + ow; ckv.Bi[2] = AP[13] + ob; ckv.C[2] = v; ckv.M[2] = NE;
        gemm_tf32<<<gDD3, 256, GEMM_SMEM>>>(ckv, DMODEL, DMODEL, 0);
        flash_attn<<<dim3(8, NHEAD, Bsz), 128, FLASH_SMEM>>>(q, k, v, attn,
                                                             SRCL, 0, tgt);
        gemm_tf32<<<gDD, 256, GEMM_SMEM>>>(
            g1(attn, AP[14] + ow, AP[15] + ob, proj, NQ), DMODEL, DMODEL, 0);
        ln_res<<<NQ, 256>>>(x, proj, n2g + ob, n2b + ob);

        // ---- feed forward ----
        gemm_tf32<<<gFF, 256, GEMM_SMEM>>>(
            g1(x, w1 + ow1, b1 + ob1, ffn, NQ), DFF, DMODEL, 1);
        gemm_tf32<<<gDD, 256, GEMM_SMEM>>>(
            g1(ffn, w2 + ow1, b2 + ob, proj, NQ), DMODEL, DFF, 0);
        ln_res<<<NQ, 256>>>(x, proj, n3g + ob, n3b + ob);
    }

    // ---- final projection to vocab ----
    gemm_tf32<<<dim3(VOC / BNt, NQ / BMt, 1), 256, GEMM_SMEM>>>(
        g1(x, fcw, fcb, (float*)d_out, NQ), VOC, DMODEL, 0);
}